// round 15
// baseline (speedup 1.0000x reference)
#include <cuda_runtime.h>
#include <cuda_bf16.h>
#include <math.h>
#include <stdint.h>

// Problem constants
#define T   2048
#define Dm  512
#define H   8
#define DH  64
#define CH  128
#define NC  (T / CH)
#define STATS_STRIDE (DH*DH + DH)   // 4160

// Scratch (device globals — no allocation allowed)
__device__ float g_stats[H * NC * STATS_STRIDE];   // KV^T [j*64+i]; ksum @4096 (by qkv)
__device__ unsigned g_syncc[4];                    // monotonic grid barriers
// Pre-split bf16 planes (packed uint32 = 2 bf16)
__device__ uint32_t g_xhi[T * Dm / 2], g_xlo[T * Dm / 2];           // x row-major [t][k]
__device__ uint32_t g_whi[4 * Dm * Dm / 2], g_wlo[4 * Dm * Dm / 2]; // W^T [m][n][k]
__device__ uint32_t g_Qhi[H * T * 32], g_Qlo[H * T * 32];           // Qp row-major
__device__ uint32_t g_Khi[H * T * 32], g_Klo[H * T * 32];           // Kp row-major
__device__ uint32_t g_VThi[H * 64 * 1024], g_VTlo[H * 64 * 1024];   // V^T, swizzled
__device__ uint32_t g_Ohi[T * Dm / 2], g_Olo[T * Dm / 2];           // attn out [t][n]

// ===========================================================================
// Helpers
// ===========================================================================
__device__ __forceinline__ uint32_t pack_bf2(float a, float b) {
    __nv_bfloat162 t;
    t.x = __float2bfloat16_rn(a);
    t.y = __float2bfloat16_rn(b);
    return *(uint32_t*)&t;
}
__device__ __forceinline__ float bfr(float x) {
    return __bfloat162float(__float2bfloat16_rn(x));
}
__device__ __forceinline__ void mma16(float c[4], const uint32_t a[4], const uint32_t b[2]) {
    asm volatile(
        "mma.sync.aligned.m16n8k16.row.col.f32.bf16.bf16.f32 "
        "{%0,%1,%2,%3}, {%4,%5,%6,%7}, {%8,%9}, {%0,%1,%2,%3};"
        : "+f"(c[0]), "+f"(c[1]), "+f"(c[2]), "+f"(c[3])
        : "r"(a[0]), "r"(a[1]), "r"(a[2]), "r"(a[3]),
          "r"(b[0]), "r"(b[1]));
}
__device__ __forceinline__ uint32_t smem_u32(const void* p) {
    uint32_t a;
    asm("{ .reg .u64 t; cvta.to.shared.u64 t, %1; cvt.u32.u64 %0, t; }"
        : "=r"(a) : "l"(p));
    return a;
}
__device__ __forceinline__ void ldm_x4(uint32_t* r, uint32_t addr) {
    asm volatile("ldmatrix.sync.aligned.m8n8.x4.shared.b16 {%0,%1,%2,%3}, [%4];"
        : "=r"(r[0]), "=r"(r[1]), "=r"(r[2]), "=r"(r[3]) : "r"(addr));
}
__device__ __forceinline__ void ldm_x4_trans(uint32_t* r, uint32_t addr) {
    asm volatile("ldmatrix.sync.aligned.m8n8.x4.trans.shared.b16 {%0,%1,%2,%3}, [%4];"
        : "=r"(r[0]), "=r"(r[1]), "=r"(r[2]), "=r"(r[3]) : "r"(addr));
}
__device__ __forceinline__ void cp16(uint32_t dst, const void* src) {
    asm volatile("cp.async.cg.shared.global [%0], [%1], 16;" :: "r"(dst), "l"(src));
}
#define CP_COMMIT() asm volatile("cp.async.commit_group;" ::: "memory")
#define CP_WAIT0()  asm volatile("cp.async.wait_group 0;" ::: "memory")

// Grid barrier: monotonic counter (graph-replay safe; 128 CTAs all resident).
__device__ __forceinline__ void gsync(int k) {
    __syncthreads();
    if (threadIdx.x == 0) {
        __threadfence();
        unsigned old = atomicAdd(&g_syncc[k], 1u);
        unsigned target = (old & ~127u) + 128u;
        while (atomicAdd(&g_syncc[k], 0u) < target) { }
        __threadfence();
    }
    __syncthreads();
}

// ===========================================================================
// Prep kernel: split W (transposed) + x into bf16 hi/lo planes. grid (16,16,5)
// ===========================================================================
__global__ void prep_kernel(const float* __restrict__ x,
                            const float* __restrict__ Wq, const float* __restrict__ Wk,
                            const float* __restrict__ Wv, const float* __restrict__ Wo)
{
    if (blockIdx.z < 4) {
        __shared__ float tile[32][33];
        const int m = blockIdx.z;
        const float* W = (m == 0) ? Wq : (m == 1) ? Wk : (m == 2) ? Wv : Wo;
        const int kb = blockIdx.x * 32, nb = blockIdx.y * 32;
        const int tid = threadIdx.x;
        const int tr = tid >> 5, tc = tid & 31;
        #pragma unroll
        for (int i = 0; i < 4; i++)
            tile[tr + i * 8][tc] = W[(kb + tr + i * 8) * Dm + nb + tc];
        __syncthreads();
        const int nr = tid >> 4, k2 = (tid & 15) * 2;
        #pragma unroll
        for (int i = 0; i < 2; i++) {
            int n = nr + i * 16;
            float v0 = tile[k2][n], v1 = tile[k2 + 1][n];
            float h0 = bfr(v0), h1 = bfr(v1);
            int widx = m * (Dm * Dm / 2) + (nb + n) * (Dm / 2) + ((kb + k2) >> 1);
            g_whi[widx] = pack_bf2(h0, h1);
            g_wlo[widx] = pack_bf2(v0 - h0, v1 - h1);
        }
    } else {
        int base = (blockIdx.y * 16 + blockIdx.x) * 256 + threadIdx.x;
        #pragma unroll
        for (int k = 0; k < 4; k++) {
            int idx = base + k * 65536;
            float4 v = ((const float4*)x)[idx];
            float h0 = bfr(v.x), h1 = bfr(v.y), h2 = bfr(v.z), h3 = bfr(v.w);
            ((uint2*)g_xhi)[idx] = make_uint2(pack_bf2(h0, h1), pack_bf2(h2, h3));
            ((uint2*)g_xlo)[idx] = make_uint2(pack_bf2(v.x - h0, v.y - h1),
                                              pack_bf2(v.z - h2, v.w - h3));
        }
    }
}

// ===========================================================================
// GEMM core: bf16 split, cp.async, ldmatrix (unchanged).
// ===========================================================================
#define GB_BUF 49152
#define GEMM_SMEM 98304
#define C_STR 68

__device__ __forceinline__ void gemm_tc(char* smem,
    const char* Ahi, const char* Alo, const char* Bhi, const char* Blo,
    int row0, int col0, float acc[2][4][4])
{
    const int tid = threadIdx.x, lane = tid & 31, wid = tid >> 5;
    const int wm = (wid & 3) * 32, wn = (wid >> 2) * 32;
    uint32_t sb = smem_u32(smem);

    #pragma unroll
    for (int mt = 0; mt < 2; mt++)
        #pragma unroll
        for (int nt = 0; nt < 4; nt++)
            #pragma unroll
            for (int i = 0; i < 4; i++) acc[mt][nt][i] = 0.f;

    uint32_t smA[8]; const char* gA[8];
    #pragma unroll
    for (int i = 0; i < 8; i++) {
        int c = tid + i * 256;
        int plane = c >> 10, rc = c & 1023, r = rc >> 3, g = rc & 7;
        smA[i] = plane * 16384 + r * 128 + ((g ^ (r & 7)) << 4);
        gA[i] = (plane ? Alo : Ahi) + (size_t)(row0 + r) * 1024 + g * 16;
    }
    uint32_t smB[4]; const char* gB[4];
    #pragma unroll
    for (int i = 0; i < 4; i++) {
        int c = tid + i * 256;
        int plane = c >> 9, rc = c & 511, n = rc >> 3, g = rc & 7;
        smB[i] = 32768 + plane * 8192 + n * 128 + ((g ^ (n & 7)) << 4);
        gB[i] = (plane ? Blo : Bhi) + (size_t)(col0 + n) * 1024 + g * 16;
    }

    #pragma unroll
    for (int i = 0; i < 8; i++) cp16(sb + smA[i], gA[i]);
    #pragma unroll
    for (int i = 0; i < 4; i++) cp16(sb + smB[i], gB[i]);
    CP_COMMIT();

    const int rA = wm + (lane & 15);
    const int nB = wn + (lane & 15);
    const int seg = lane >> 4;
    const int xv = lane & 7;

    for (int s = 0; s < 8; s++) {
        CP_WAIT0();
        __syncthreads();
        if (s + 1 < 8) {
            int koff = (s + 1) * 128;
            uint32_t boff = (uint32_t)(((s + 1) & 1) * GB_BUF);
            #pragma unroll
            for (int i = 0; i < 8; i++) cp16(sb + boff + smA[i], gA[i] + koff);
            #pragma unroll
            for (int i = 0; i < 4; i++) cp16(sb + boff + smB[i], gB[i] + koff);
            CP_COMMIT();
        }
        uint32_t bufb = sb + (uint32_t)((s & 1) * GB_BUF);

        #pragma unroll
        for (int ks = 0; ks < 4; ks++) {
            uint32_t sw = (uint32_t)((((ks << 1) + seg) ^ xv) << 4);
            uint32_t ah[2][4], al[2][4];
            {
                uint32_t a0 = bufb + rA * 128 + sw;
                ldm_x4(ah[0], a0);
                ldm_x4(al[0], a0 + 16384);
                uint32_t a1 = a0 + 16 * 128;
                ldm_x4(ah[1], a1);
                ldm_x4(al[1], a1 + 16384);
            }
            uint32_t q[4], bh[4][2], bl[4][2];
            {
                uint32_t b0 = bufb + 32768 + nB * 128 + sw;
                ldm_x4(q, b0);
                bh[0][0] = q[0]; bh[0][1] = q[2]; bh[1][0] = q[1]; bh[1][1] = q[3];
                ldm_x4(q, b0 + 8192);
                bl[0][0] = q[0]; bl[0][1] = q[2]; bl[1][0] = q[1]; bl[1][1] = q[3];
                uint32_t b1 = b0 + 16 * 128;
                ldm_x4(q, b1);
                bh[2][0] = q[0]; bh[2][1] = q[2]; bh[3][0] = q[1]; bh[3][1] = q[3];
                ldm_x4(q, b1 + 8192);
                bl[2][0] = q[0]; bl[2][1] = q[2]; bl[3][0] = q[1]; bl[3][1] = q[3];
            }
            #pragma unroll
            for (int mt = 0; mt < 2; mt++)
                #pragma unroll
                for (int nt = 0; nt < 4; nt++) {
                    mma16(acc[mt][nt], ah[mt], bh[nt]);
                    mma16(acc[mt][nt], al[mt], bh[nt]);
                    mma16(acc[mt][nt], ah[mt], bl[nt]);
                }
        }
    }
}

__device__ __forceinline__ void acc_to_smem(float* Cs, const float acc[2][4][4])
{
    const int lane = threadIdx.x & 31;
    const int wid  = threadIdx.x >> 5;
    const int wm   = (wid & 3) * 32;
    const int wn   = (wid >> 2) * 32;
    const int lr = lane >> 2, lc = lane & 3;

    #pragma unroll
    for (int mt = 0; mt < 2; mt++)
        #pragma unroll
        for (int nt = 0; nt < 4; nt++) {
            int r = wm + mt * 16 + lr;
            int n = wn + nt * 8 + 2 * lc;
            #pragma unroll
            for (int i = 0; i < 4; i++)
                Cs[(r + (i >= 2 ? 8 : 0)) * C_STR + n + (i & 1)] = acc[mt][nt][i];
        }
}

// ---------------------------------------------------------------------------
// Kernel 1: fused QKV projection (unchanged). grid = (T/128, H, 3).
// ---------------------------------------------------------------------------
__global__ void __launch_bounds__(256, 2) qkv_tc_kernel(
    const float* __restrict__ bq, const float* __restrict__ bk,
    const float* __restrict__ bv)
{
    extern __shared__ char smem[];

    const int which = blockIdx.z;
    const float* b = (which == 0) ? bq : (which == 1) ? bk : bv;

    const int row0 = blockIdx.x * 128;
    const int h    = blockIdx.y;
    const int col0 = h * 64;

    float acc[2][4][4];
    gemm_tc(smem, (const char*)g_xhi, (const char*)g_xlo,
            (const char*)(g_whi + which * (Dm * Dm / 2)),
            (const char*)(g_wlo + which * (Dm * Dm / 2)),
            row0, col0, acc);

    float* Cs = (float*)smem;
    acc_to_smem(Cs, acc);
    __syncthreads();

    const int tid = threadIdx.x;
    float* Act = (float*)(smem + 36864);
    const int c4 = (tid & 15) << 2;
    float ksp0 = 0.f, ksp1 = 0.f, ksp2 = 0.f, ksp3 = 0.f;
    const float bb0 = b[col0 + c4], bb1 = b[col0 + c4 + 1];
    const float bb2 = b[col0 + c4 + 2], bb3 = b[col0 + c4 + 3];

    #pragma unroll
    for (int it = 0; it < 8; it++) {
        int r = (tid >> 4) + it * 16;
        float4 v = *(float4*)&Cs[r * C_STR + c4];
        v.x += bb0; v.y += bb1; v.z += bb2; v.w += bb3;
        if (which < 2) {
            v.x = (v.x > 0.f) ? (v.x + 1.f) : __expf(v.x);
            v.y = (v.y > 0.f) ? (v.y + 1.f) : __expf(v.y);
            v.z = (v.z > 0.f) ? (v.z + 1.f) : __expf(v.z);
            v.w = (v.w > 0.f) ? (v.w + 1.f) : __expf(v.w);
        }
        if (which == 1) { ksp0 += v.x; ksp1 += v.y; ksp2 += v.z; ksp3 += v.w; }
        if (which < 2) {
            float h0 = bfr(v.x), h1 = bfr(v.y), h2 = bfr(v.z), h3 = bfr(v.w);
            uint32_t* hip = which ? g_Khi : g_Qhi;
            uint32_t* lop = which ? g_Klo : g_Qlo;
            int w = (h * T + row0 + r) * 32 + (c4 >> 1);
            *(uint2*)&hip[w] = make_uint2(pack_bf2(h0, h1), pack_bf2(h2, h3));
            *(uint2*)&lop[w] = make_uint2(pack_bf2(v.x - h0, v.y - h1),
                                          pack_bf2(v.z - h2, v.w - h3));
        } else {
            Act[r * 65 + c4]     = v.x;
            Act[r * 65 + c4 + 1] = v.y;
            Act[r * 65 + c4 + 2] = v.z;
            Act[r * 65 + c4 + 3] = v.w;
        }
    }

    if (which == 2) {
        __syncthreads();
        const int cchunk = blockIdx.x;
        #pragma unroll
        for (int i = 0; i < 16; i++) {
            int s = tid + i * 256;
            int d = s >> 6, lw = s & 63;
            float f0 = Act[(2 * lw) * 65 + d];
            float f1 = Act[(2 * lw + 1) * 65 + d];
            float h0 = bfr(f0), h1 = bfr(f1);
            int gw = (h * 64 + d) * 1024 + cchunk * 64 + (lw ^ ((d >> 3) & 3));
            g_VThi[gw] = pack_bf2(h0, h1);
            g_VTlo[gw] = pack_bf2(f0 - h0, f1 - h1);
        }
    }
    if (which == 1) {
        float* ksm = (float*)(smem + 73728);
        *(float4*)&ksm[(tid >> 4) * 64 + c4] = make_float4(ksp0, ksp1, ksp2, ksp3);
        __syncthreads();
        if (tid < 64) {
            float s = 0.f;
            #pragma unroll
            for (int g2 = 0; g2 < 16; g2++) s += ksm[g2 * 64 + tid];
            g_stats[(h * NC + blockIdx.x) * STATS_STRIDE + 4096 + tid] = s;
        }
    }
}

// ===========================================================================
// FUSED tail: chunk -> (per-CTA prefix reduction) -> attn -> out.
// One grid barrier removed: each CTA reduces its own exclusive prefix from
// g_stats (L2-resident), with identical fp32 summation order + single split.
// ===========================================================================
#define OFF_QH 0
#define OFF_QL (OFF_QH + 128*36)
#define OFF_KH (OFF_QL + 128*36)
#define OFF_KL (OFF_KH + 128*36)
#define OFF_VH (OFF_KL + 128*36)
#define OFF_VL (OFF_VH + 64*68)
#define OFF_SH (OFF_VL + 64*68)
#define OFF_SL (OFF_SH + 72*36)
#define OFF_SC (OFF_SL + 72*36)           // fp32 prefix accumulator (4160 floats)
#define ATTN_SMEM ((OFF_SC + 4160) * 4)   // 145920 B

__global__ void __launch_bounds__(256, 1) fused_tail_kernel(
    const float* __restrict__ bo, float* __restrict__ y)
{
    extern __shared__ uint32_t smw[];

    const int bid = blockIdx.x;
    const int c = bid & 15, h = bid >> 4;
    const int tid = threadIdx.x;
    const uint32_t sbw = smem_u32(smw);
    const int lane = tid & 31, wid = tid >> 5;
    const int lr = lane >> 2, lc = lane & 3;

    // Phase 1: stage VT + Q + K, chunk M = V^T K (trans-ldmatrix B)
    {
        const int vsrc = h * 64 * 1024 + c * 64;
        #pragma unroll
        for (int i = 0; i < 8; i++) {
            int slot = tid + i * 256;
            int p = slot >> 10, d = (slot >> 4) & 63, g = slot & 15;
            cp16(sbw + ((p ? OFF_VL : OFF_VH) + d * 68 + g * 4) * 4,
                 (p ? g_VTlo : g_VThi) + vsrc + d * 1024 + g * 4);
        }
        const int qsrc = (h * T + c * CH) * 32;
        #pragma unroll
        for (int i = 0; i < 8; i++) {
            int slot = tid + i * 256;
            int p = slot >> 10, r = (slot >> 3) & 127, g = slot & 7;
            int so = qsrc + r * 32 + g * 4;
            cp16(sbw + ((p ? OFF_QL : OFF_QH) + r * 36 + g * 4) * 4,
                 (p ? g_Qlo : g_Qhi) + so);
            cp16(sbw + ((p ? OFF_KL : OFF_KH) + r * 36 + g * 4) * 4,
                 (p ? g_Klo : g_Khi) + so);
        }
        CP_COMMIT();
        CP_WAIT0();
        __syncthreads();

        const int wm = (wid & 3) * 16;
        const int wn = (wid >> 2) * 32;
        const int m0 = wm + lr, m1 = m0 + 8;

        uint32_t ah[8][4], al[8][4];
        {
            const int sw0 = (m0 >> 3) & 3;
            const int sw1 = (m1 >> 3) & 3;
            const uint32_t* h0 = smw + OFF_VH + m0 * 68;
            const uint32_t* h1 = smw + OFF_VH + m1 * 68;
            const uint32_t* l0 = smw + OFF_VL + m0 * 68;
            const uint32_t* l1 = smw + OFF_VL + m1 * 68;
            #pragma unroll
            for (int kh = 0; kh < 8; kh++) {
                int w0 = (kh * 8 + lc) ^ sw0;
                int w1 = (kh * 8 + lc) ^ sw1;
                ah[kh][0] = h0[w0];     ah[kh][1] = h1[w1];
                ah[kh][2] = h0[w0 + 4]; ah[kh][3] = h1[w1 + 4];
                al[kh][0] = l0[w0];     al[kh][1] = l1[w1];
                al[kh][2] = l0[w0 + 4]; al[kh][3] = l1[w1 + 4];
            }
        }

        float cb[4][4];
        #pragma unroll
        for (int nt = 0; nt < 4; nt++)
            #pragma unroll
            for (int i = 0; i < 4; i++) cb[nt][i] = 0.f;

        const int trow  = (lane & 7) + 8 * ((lane >> 3) & 1);
        const int tcol8 = 8 * (lane >> 4);
        #pragma unroll
        for (int p = 0; p < 2; p++) {
            const int colb = wn + p * 16 + tcol8;
            #pragma unroll
            for (int kb = 0; kb < 8; kb++) {
                int row = kb * 16 + trow;
                uint32_t aH = sbw + (OFF_KH + row * 36) * 4 + colb * 2;
                uint32_t aL = sbw + (OFF_KL + row * 36) * 4 + colb * 2;
                uint32_t qh4[4], ql4[4];
                ldm_x4_trans(qh4, aH);
                ldm_x4_trans(ql4, aL);
                uint32_t bh0[2] = {qh4[0], qh4[1]}, bh1[2] = {qh4[2], qh4[3]};
                uint32_t bl0[2] = {ql4[0], ql4[1]}, bl1[2] = {ql4[2], ql4[3]};
                mma16(cb[2*p],     ah[kb], bh0);
                mma16(cb[2*p],     al[kb], bh0);
                mma16(cb[2*p],     ah[kb], bl0);
                mma16(cb[2*p + 1], ah[kb], bh1);
                mma16(cb[2*p + 1], al[kb], bh1);
                mma16(cb[2*p + 1], ah[kb], bl1);
            }
        }

        float* outp = g_stats + (h * NC + c) * STATS_STRIDE;
        #pragma unroll
        for (int nt = 0; nt < 4; nt++) {
            int n0 = wn + nt * 8 + 2 * lc;
            *(float2*)&outp[m0 * 64 + n0] = make_float2(cb[nt][0], cb[nt][1]);
            *(float2*)&outp[m1 * 64 + n0] = make_float2(cb[nt][2], cb[nt][3]);
        }
    }

    gsync(0);

    // Phase 2: per-CTA exclusive-prefix reduction -> split St in smem.
    {
        float* Sacc = (float*)(smw + OFF_SC);
        const float* statsh = g_stats + (h * NC) * STATS_STRIDE;
        #pragma unroll
        for (int i = 0; i < 17; i++) {
            int e = tid + i * 256;
            if (e < 4160) {
                float s = 0.f;
                for (int cc = 0; cc < c; cc++)
                    s += statsh[cc * STATS_STRIDE + e];
                Sacc[e] = s;
            }
        }
        __syncthreads();

        // Build split St rows: 0..63 = S^T (Sacc[r*64 + 2w..]), 64 = z, 65..71 = 0
        #pragma unroll
        for (int i = 0; i < 9; i++) {
            int slot = tid + i * 256;
            if (slot < 2304) {
                int r = slot >> 5, w = slot & 31;
                float f0 = 0.f, f1 = 0.f;
                if (r < 64)      { f0 = Sacc[r * 64 + 2 * w];  f1 = Sacc[r * 64 + 2 * w + 1]; }
                else if (r == 64){ f0 = Sacc[4096 + 2 * w];    f1 = Sacc[4096 + 2 * w + 1]; }
                float h0 = bfr(f0), h1 = bfr(f1);
                smw[OFF_SH + r * 36 + w] = pack_bf2(h0, h1);
                smw[OFF_SL + r * 36 + w] = pack_bf2(f0 - h0, f1 - h1);
            }
        }
        __syncthreads();
    }

    // Phase 3: attention (A-fragments in registers; Q/K/V/St all resident)
    {
        const int wm = wid * 16;
        const int t0 = wm + lr, t1 = t0 + 8;

        uint32_t qh[4][4], ql[4][4];
        {
            const uint32_t* ph = smw + OFF_QH + t0 * 36 + lc;
            const uint32_t* pl = smw + OFF_QL + t0 * 36 + lc;
            #pragma unroll
            for (int kh = 0; kh < 4; kh++) {
                int o = kh * 8;
                qh[kh][0] = ph[o];     qh[kh][1] = ph[o + 288];
                qh[kh][2] = ph[o + 4]; qh[kh][3] = ph[o + 292];
                ql[kh][0] = pl[o];     ql[kh][1] = pl[o + 288];
                ql[kh][2] = pl[o + 4]; ql[kh][3] = pl[o + 292];
            }
        }

        float ca[16][4];
        #pragma unroll
        for (int nt = 0; nt < 16; nt++)
            #pragma unroll
            for (int i = 0; i < 4; i++) ca[nt][i] = 0.f;

        const int ntmax = 2 * wid + 1;
        #pragma unroll
        for (int nt = 0; nt < 16; nt++) {
            if (nt <= ntmax) {
                const uint32_t* bhp = smw + OFF_KH + (nt * 8 + lr) * 36 + lc;
                const uint32_t* blp = smw + OFF_KL + (nt * 8 + lr) * 36 + lc;
                #pragma unroll
                for (int kh = 0; kh < 4; kh++) {
                    uint32_t bh[2] = {bhp[kh * 8], bhp[kh * 8 + 4]};
                    uint32_t bl[2] = {blp[kh * 8], blp[kh * 8 + 4]};
                    mma16(ca[nt], qh[kh], bh);
                    mma16(ca[nt], ql[kh], bh);
                    mma16(ca[nt], qh[kh], bl);
                }
            }
        }

        float rs0 = 0.f, rs1 = 0.f;
        uint32_t aAh[8][4], aAl[8][4];
        #pragma unroll
        for (int nt = 0; nt < 16; nt++) {
            int s0 = nt * 8 + 2 * lc;
            float c0 = (s0     <= t0) ? ca[nt][0] : 0.f;
            float c1 = (s0 + 1 <= t0) ? ca[nt][1] : 0.f;
            float c2 = (s0     <= t1) ? ca[nt][2] : 0.f;
            float c3 = (s0 + 1 <= t1) ? ca[nt][3] : 0.f;
            rs0 += c0 + c1;
            rs1 += c2 + c3;
            float h0 = bfr(c0), h1 = bfr(c1), h2 = bfr(c2), h3 = bfr(c3);
            int kb = nt >> 1, half = nt & 1;
            aAh[kb][half * 2 + 0] = pack_bf2(h0, h1);
            aAh[kb][half * 2 + 1] = pack_bf2(h2, h3);
            aAl[kb][half * 2 + 0] = pack_bf2(c0 - h0, c1 - h1);
            aAl[kb][half * 2 + 1] = pack_bf2(c2 - h2, c3 - h3);
        }
        rs0 += __shfl_xor_sync(0xffffffffu, rs0, 1);
        rs0 += __shfl_xor_sync(0xffffffffu, rs0, 2);
        rs1 += __shfl_xor_sync(0xffffffffu, rs1, 1);
        rs1 += __shfl_xor_sync(0xffffffffu, rs1, 2);

        float cb[9][4];
        #pragma unroll
        for (int nt = 0; nt < 9; nt++)
            #pragma unroll
            for (int i = 0; i < 4; i++) cb[nt][i] = 0.f;

        #pragma unroll
        for (int nt = 0; nt < 8; nt++) {
            int n = nt * 8 + lr;
            int swB = nt & 3;
            const uint32_t* vh = smw + OFF_VH + n * 68;
            const uint32_t* vl = smw + OFF_VL + n * 68;
            #pragma unroll
            for (int kh = 0; kh < 8; kh++) {
                if (kh <= wid) {
                    int w = (kh * 8 + lc) ^ swB;
                    uint32_t bh[2] = {vh[w], vh[w + 4]};
                    uint32_t bl[2] = {vl[w], vl[w + 4]};
                    mma16(cb[nt], aAh[kh], bh);
                    mma16(cb[nt], aAl[kh], bh);
                    mma16(cb[nt], aAh[kh], bl);
                }
            }
            const uint32_t* sh = smw + OFF_SH + n * 36 + lc;
            const uint32_t* sl = smw + OFF_SL + n * 36 + lc;
            #pragma unroll
            for (int ks = 0; ks < 4; ks++) {
                uint32_t bh[2] = {sh[ks * 8], sh[ks * 8 + 4]};
                uint32_t bl[2] = {sl[ks * 8], sl[ks * 8 + 4]};
                mma16(cb[nt], qh[ks], bh);
                mma16(cb[nt], ql[ks], bh);
                mma16(cb[nt], qh[ks], bl);
            }
        }
        {
            int n = 64 + lr;
            const uint32_t* sh = smw + OFF_SH + n * 36 + lc;
            const uint32_t* sl = smw + OFF_SL + n * 36 + lc;
            #pragma unroll
            for (int ks = 0; ks < 4; ks++) {
                uint32_t bh[2] = {sh[ks * 8], sh[ks * 8 + 4]};
                uint32_t bl[2] = {sl[ks * 8], sl[ks * 8 + 4]};
                mma16(cb[8], qh[ks], bh);
                mma16(cb[8], ql[ks], bh);
                mma16(cb[8], qh[ks], bl);
            }
        }

        float di0 = __shfl_sync(0xffffffffu, cb[8][0], lane & ~3);
        float di1 = __shfl_sync(0xffffffffu, cb[8][2], lane & ~3);
        float inv0 = 1.f / fmaxf(rs0 + di0, 1e-6f);
        float inv1 = 1.f / fmaxf(rs1 + di1, 1e-6f);

        const int base = (c * CH) * (Dm / 2) + h * 32;
        #pragma unroll
        for (int nt = 0; nt < 8; nt++) {
            int jw = (nt * 8 + 2 * lc) >> 1;
            {
                float o0 = cb[nt][0] * inv0, o1 = cb[nt][1] * inv0;
                float h0 = bfr(o0), h1 = bfr(o1);
                g_Ohi[base + t0 * (Dm / 2) + jw] = pack_bf2(h0, h1);
                g_Olo[base + t0 * (Dm / 2) + jw] = pack_bf2(o0 - h0, o1 - h1);
            }
            {
                float o0 = cb[nt][2] * inv1, o1 = cb[nt][3] * inv1;
                float h0 = bfr(o0), h1 = bfr(o1);
                g_Ohi[base + t1 * (Dm / 2) + jw] = pack_bf2(h0, h1);
                g_Olo[base + t1 * (Dm / 2) + jw] = pack_bf2(o0 - h0, o1 - h1);
            }
        }
    }

    gsync(1);

    // Phase 4: output projection
    {
        const int row0 = (bid & 15) * 128;
        const int col0 = (bid >> 4) * 64;

        float acc[2][4][4];
        gemm_tc((char*)smw, (const char*)g_Ohi, (const char*)g_Olo,
                (const char*)(g_whi + 3 * (Dm * Dm / 2)),
                (const char*)(g_wlo + 3 * (Dm * Dm / 2)),
                row0, col0, acc);

        float* Cs = (float*)smw;
        acc_to_smem(Cs, acc);
        __syncthreads();

        #pragma unroll
        for (int it = 0; it < 8; it++) {
            int idx = tid + it * 256;
            int r = idx >> 4, c4 = (idx & 15) << 2;
            float4 v = *(float4*)&Cs[r * C_STR + c4];
            v.x += bo[col0 + c4 + 0];
            v.y += bo[col0 + c4 + 1];
            v.z += bo[col0 + c4 + 2];
            v.w += bo[col0 + c4 + 3];
            *(float4*)&y[(row0 + r) * Dm + col0 + c4] = v;
        }
    }
}

// ---------------------------------------------------------------------------
extern "C" void kernel_launch(void* const* d_in, const int* in_sizes, int n_in,
                              void* d_out, int out_size)
{
    const float* x  = (const float*)d_in[0];
    const float* Wq = (const float*)d_in[1];
    const float* bq = (const float*)d_in[2];
    const float* Wk = (const float*)d_in[3];
    const float* bk = (const float*)d_in[4];
    const float* Wv = (const float*)d_in[5];
    const float* bv = (const float*)d_in[6];
    const float* Wo = (const float*)d_in[7];
    const float* bo = (const float*)d_in[8];
    float* y = (float*)d_out;

    cudaFuncSetAttribute(qkv_tc_kernel,
                         cudaFuncAttributeMaxDynamicSharedMemorySize, GEMM_SMEM);
    cudaFuncSetAttribute(fused_tail_kernel,
                         cudaFuncAttributeMaxDynamicSharedMemorySize, ATTN_SMEM);

    prep_kernel      <<<dim3(16, 16, 5), 256>>>(x, Wq, Wk, Wv, Wo);
    qkv_tc_kernel    <<<dim3(T/128, H, 3), 256, GEMM_SMEM>>>(bq, bk, bv);
    fused_tail_kernel<<<128, 256, ATTN_SMEM>>>(bo, y);
}

// round 16
// speedup vs baseline: 1.5017x; 1.5017x over previous
#include <cuda_runtime.h>
#include <cuda_bf16.h>
#include <math.h>
#include <stdint.h>

// Problem constants
#define T   2048
#define Dm  512
#define H   8
#define DH  64
#define CH  128
#define NC  (T / CH)
#define STATS_STRIDE (DH*DH + DH)   // 4160

// Scratch (device globals — no allocation allowed)
__device__ float g_stats[H * NC * STATS_STRIDE];   // KV^T [j*64+i]; ksum @4096 (by qkv)
__device__ unsigned g_syncc[4];                    // monotonic grid barriers
// Pre-split bf16 planes (packed uint32 = 2 bf16)
__device__ uint32_t g_xhi[T * Dm / 2], g_xlo[T * Dm / 2];           // x row-major [t][k]
__device__ uint32_t g_whi[4 * Dm * Dm / 2], g_wlo[4 * Dm * Dm / 2]; // W^T [m][n][k]
__device__ uint32_t g_Qhi[H * T * 32], g_Qlo[H * T * 32];           // Qp row-major
__device__ uint32_t g_Khi[H * T * 32], g_Klo[H * T * 32];           // Kp row-major
__device__ uint32_t g_VThi[H * 64 * 1024], g_VTlo[H * 64 * 1024];   // V^T, swizzled
__device__ uint32_t g_Shi[H * NC * 72 * 32], g_Slo[H * NC * 72 * 32]; // St planes
__device__ uint32_t g_Ohi[T * Dm / 2], g_Olo[T * Dm / 2];           // attn out [t][n]

// ===========================================================================
// Helpers
// ===========================================================================
__device__ __forceinline__ uint32_t pack_bf2(float a, float b) {
    __nv_bfloat162 t;
    t.x = __float2bfloat16_rn(a);
    t.y = __float2bfloat16_rn(b);
    return *(uint32_t*)&t;
}
__device__ __forceinline__ float bfr(float x) {
    return __bfloat162float(__float2bfloat16_rn(x));
}
__device__ __forceinline__ void mma16(float c[4], const uint32_t a[4], const uint32_t b[2]) {
    asm volatile(
        "mma.sync.aligned.m16n8k16.row.col.f32.bf16.bf16.f32 "
        "{%0,%1,%2,%3}, {%4,%5,%6,%7}, {%8,%9}, {%0,%1,%2,%3};"
        : "+f"(c[0]), "+f"(c[1]), "+f"(c[2]), "+f"(c[3])
        : "r"(a[0]), "r"(a[1]), "r"(a[2]), "r"(a[3]),
          "r"(b[0]), "r"(b[1]));
}
__device__ __forceinline__ uint32_t smem_u32(const void* p) {
    uint32_t a;
    asm("{ .reg .u64 t; cvta.to.shared.u64 t, %1; cvt.u32.u64 %0, t; }"
        : "=r"(a) : "l"(p));
    return a;
}
__device__ __forceinline__ void ldm_x4(uint32_t* r, uint32_t addr) {
    asm volatile("ldmatrix.sync.aligned.m8n8.x4.shared.b16 {%0,%1,%2,%3}, [%4];"
        : "=r"(r[0]), "=r"(r[1]), "=r"(r[2]), "=r"(r[3]) : "r"(addr));
}
__device__ __forceinline__ void ldm_x4_trans(uint32_t* r, uint32_t addr) {
    asm volatile("ldmatrix.sync.aligned.m8n8.x4.trans.shared.b16 {%0,%1,%2,%3}, [%4];"
        : "=r"(r[0]), "=r"(r[1]), "=r"(r[2]), "=r"(r[3]) : "r"(addr));
}
__device__ __forceinline__ void cp16(uint32_t dst, const void* src) {
    asm volatile("cp.async.cg.shared.global [%0], [%1], 16;" :: "r"(dst), "l"(src));
}
#define CP_COMMIT() asm volatile("cp.async.commit_group;" ::: "memory")
#define CP_WAIT0()  asm volatile("cp.async.wait_group 0;" ::: "memory")

// Grid barrier: monotonic counter (graph-replay safe; 128 CTAs all resident).
__device__ __forceinline__ void gsync(int k) {
    __syncthreads();
    if (threadIdx.x == 0) {
        __threadfence();
        unsigned old = atomicAdd(&g_syncc[k], 1u);
        unsigned target = (old & ~127u) + 128u;
        while (atomicAdd(&g_syncc[k], 0u) < target) { __nanosleep(64); }
        __threadfence();
    }
    __syncthreads();
}

// ===========================================================================
// Prep kernel: split W (transposed) + x into bf16 hi/lo planes. grid (16,16,5)
// ===========================================================================
__global__ void prep_kernel(const float* __restrict__ x,
                            const float* __restrict__ Wq, const float* __restrict__ Wk,
                            const float* __restrict__ Wv, const float* __restrict__ Wo)
{
    if (blockIdx.z < 4) {
        __shared__ float tile[32][33];
        const int m = blockIdx.z;
        const float* W = (m == 0) ? Wq : (m == 1) ? Wk : (m == 2) ? Wv : Wo;
        const int kb = blockIdx.x * 32, nb = blockIdx.y * 32;
        const int tid = threadIdx.x;
        const int tr = tid >> 5, tc = tid & 31;
        #pragma unroll
        for (int i = 0; i < 4; i++)
            tile[tr + i * 8][tc] = W[(kb + tr + i * 8) * Dm + nb + tc];
        __syncthreads();
        const int nr = tid >> 4, k2 = (tid & 15) * 2;
        #pragma unroll
        for (int i = 0; i < 2; i++) {
            int n = nr + i * 16;
            float v0 = tile[k2][n], v1 = tile[k2 + 1][n];
            float h0 = bfr(v0), h1 = bfr(v1);
            int widx = m * (Dm * Dm / 2) + (nb + n) * (Dm / 2) + ((kb + k2) >> 1);
            g_whi[widx] = pack_bf2(h0, h1);
            g_wlo[widx] = pack_bf2(v0 - h0, v1 - h1);
        }
    } else {
        int base = (blockIdx.y * 16 + blockIdx.x) * 256 + threadIdx.x;
        #pragma unroll
        for (int k = 0; k < 4; k++) {
            int idx = base + k * 65536;
            float4 v = ((const float4*)x)[idx];
            float h0 = bfr(v.x), h1 = bfr(v.y), h2 = bfr(v.z), h3 = bfr(v.w);
            ((uint2*)g_xhi)[idx] = make_uint2(pack_bf2(h0, h1), pack_bf2(h2, h3));
            ((uint2*)g_xlo)[idx] = make_uint2(pack_bf2(v.x - h0, v.y - h1),
                                              pack_bf2(v.z - h2, v.w - h3));
        }
    }
}

// ===========================================================================
// GEMM core: bf16 split, cp.async, ldmatrix (unchanged).
// ===========================================================================
#define GB_BUF 49152
#define GEMM_SMEM 98304
#define C_STR 68

__device__ __forceinline__ void gemm_tc(char* smem,
    const char* Ahi, const char* Alo, const char* Bhi, const char* Blo,
    int row0, int col0, float acc[2][4][4])
{
    const int tid = threadIdx.x, lane = tid & 31, wid = tid >> 5;
    const int wm = (wid & 3) * 32, wn = (wid >> 2) * 32;
    uint32_t sb = smem_u32(smem);

    #pragma unroll
    for (int mt = 0; mt < 2; mt++)
        #pragma unroll
        for (int nt = 0; nt < 4; nt++)
            #pragma unroll
            for (int i = 0; i < 4; i++) acc[mt][nt][i] = 0.f;

    uint32_t smA[8]; const char* gA[8];
    #pragma unroll
    for (int i = 0; i < 8; i++) {
        int c = tid + i * 256;
        int plane = c >> 10, rc = c & 1023, r = rc >> 3, g = rc & 7;
        smA[i] = plane * 16384 + r * 128 + ((g ^ (r & 7)) << 4);
        gA[i] = (plane ? Alo : Ahi) + (size_t)(row0 + r) * 1024 + g * 16;
    }
    uint32_t smB[4]; const char* gB[4];
    #pragma unroll
    for (int i = 0; i < 4; i++) {
        int c = tid + i * 256;
        int plane = c >> 9, rc = c & 511, n = rc >> 3, g = rc & 7;
        smB[i] = 32768 + plane * 8192 + n * 128 + ((g ^ (n & 7)) << 4);
        gB[i] = (plane ? Blo : Bhi) + (size_t)(col0 + n) * 1024 + g * 16;
    }

    #pragma unroll
    for (int i = 0; i < 8; i++) cp16(sb + smA[i], gA[i]);
    #pragma unroll
    for (int i = 0; i < 4; i++) cp16(sb + smB[i], gB[i]);
    CP_COMMIT();

    const int rA = wm + (lane & 15);
    const int nB = wn + (lane & 15);
    const int seg = lane >> 4;
    const int xv = lane & 7;

    for (int s = 0; s < 8; s++) {
        CP_WAIT0();
        __syncthreads();
        if (s + 1 < 8) {
            int koff = (s + 1) * 128;
            uint32_t boff = (uint32_t)(((s + 1) & 1) * GB_BUF);
            #pragma unroll
            for (int i = 0; i < 8; i++) cp16(sb + boff + smA[i], gA[i] + koff);
            #pragma unroll
            for (int i = 0; i < 4; i++) cp16(sb + boff + smB[i], gB[i] + koff);
            CP_COMMIT();
        }
        uint32_t bufb = sb + (uint32_t)((s & 1) * GB_BUF);

        #pragma unroll
        for (int ks = 0; ks < 4; ks++) {
            uint32_t sw = (uint32_t)((((ks << 1) + seg) ^ xv) << 4);
            uint32_t ah[2][4], al[2][4];
            {
                uint32_t a0 = bufb + rA * 128 + sw;
                ldm_x4(ah[0], a0);
                ldm_x4(al[0], a0 + 16384);
                uint32_t a1 = a0 + 16 * 128;
                ldm_x4(ah[1], a1);
                ldm_x4(al[1], a1 + 16384);
            }
            uint32_t q[4], bh[4][2], bl[4][2];
            {
                uint32_t b0 = bufb + 32768 + nB * 128 + sw;
                ldm_x4(q, b0);
                bh[0][0] = q[0]; bh[0][1] = q[2]; bh[1][0] = q[1]; bh[1][1] = q[3];
                ldm_x4(q, b0 + 8192);
                bl[0][0] = q[0]; bl[0][1] = q[2]; bl[1][0] = q[1]; bl[1][1] = q[3];
                uint32_t b1 = b0 + 16 * 128;
                ldm_x4(q, b1);
                bh[2][0] = q[0]; bh[2][1] = q[2]; bh[3][0] = q[1]; bh[3][1] = q[3];
                ldm_x4(q, b1 + 8192);
                bl[2][0] = q[0]; bl[2][1] = q[2]; bl[3][0] = q[1]; bl[3][1] = q[3];
            }
            #pragma unroll
            for (int mt = 0; mt < 2; mt++)
                #pragma unroll
                for (int nt = 0; nt < 4; nt++) {
                    mma16(acc[mt][nt], ah[mt], bh[nt]);
                    mma16(acc[mt][nt], al[mt], bh[nt]);
                    mma16(acc[mt][nt], ah[mt], bl[nt]);
                }
        }
    }
}

__device__ __forceinline__ void acc_to_smem(float* Cs, const float acc[2][4][4])
{
    const int lane = threadIdx.x & 31;
    const int wid  = threadIdx.x >> 5;
    const int wm   = (wid & 3) * 32;
    const int wn   = (wid >> 2) * 32;
    const int lr = lane >> 2, lc = lane & 3;

    #pragma unroll
    for (int mt = 0; mt < 2; mt++)
        #pragma unroll
        for (int nt = 0; nt < 4; nt++) {
            int r = wm + mt * 16 + lr;
            int n = wn + nt * 8 + 2 * lc;
            #pragma unroll
            for (int i = 0; i < 4; i++)
                Cs[(r + (i >= 2 ? 8 : 0)) * C_STR + n + (i & 1)] = acc[mt][nt][i];
        }
}

// ---------------------------------------------------------------------------
// Kernel 1: fused QKV projection (R14). grid = (T/128, H, 3).
// ---------------------------------------------------------------------------
__global__ void __launch_bounds__(256, 2) qkv_tc_kernel(
    const float* __restrict__ bq, const float* __restrict__ bk,
    const float* __restrict__ bv)
{
    extern __shared__ char smem[];

    const int which = blockIdx.z;
    const float* b = (which == 0) ? bq : (which == 1) ? bk : bv;

    const int row0 = blockIdx.x * 128;
    const int h    = blockIdx.y;
    const int col0 = h * 64;

    float acc[2][4][4];
    gemm_tc(smem, (const char*)g_xhi, (const char*)g_xlo,
            (const char*)(g_whi + which * (Dm * Dm / 2)),
            (const char*)(g_wlo + which * (Dm * Dm / 2)),
            row0, col0, acc);

    float* Cs = (float*)smem;
    acc_to_smem(Cs, acc);
    __syncthreads();

    const int tid = threadIdx.x;
    float* Act = (float*)(smem + 36864);
    const int c4 = (tid & 15) << 2;
    float ksp0 = 0.f, ksp1 = 0.f, ksp2 = 0.f, ksp3 = 0.f;
    const float bb0 = b[col0 + c4], bb1 = b[col0 + c4 + 1];
    const float bb2 = b[col0 + c4 + 2], bb3 = b[col0 + c4 + 3];

    #pragma unroll
    for (int it = 0; it < 8; it++) {
        int r = (tid >> 4) + it * 16;
        float4 v = *(float4*)&Cs[r * C_STR + c4];
        v.x += bb0; v.y += bb1; v.z += bb2; v.w += bb3;
        if (which < 2) {
            v.x = (v.x > 0.f) ? (v.x + 1.f) : __expf(v.x);
            v.y = (v.y > 0.f) ? (v.y + 1.f) : __expf(v.y);
            v.z = (v.z > 0.f) ? (v.z + 1.f) : __expf(v.z);
            v.w = (v.w > 0.f) ? (v.w + 1.f) : __expf(v.w);
        }
        if (which == 1) { ksp0 += v.x; ksp1 += v.y; ksp2 += v.z; ksp3 += v.w; }
        if (which < 2) {
            float h0 = bfr(v.x), h1 = bfr(v.y), h2 = bfr(v.z), h3 = bfr(v.w);
            uint32_t* hip = which ? g_Khi : g_Qhi;
            uint32_t* lop = which ? g_Klo : g_Qlo;
            int w = (h * T + row0 + r) * 32 + (c4 >> 1);
            *(uint2*)&hip[w] = make_uint2(pack_bf2(h0, h1), pack_bf2(h2, h3));
            *(uint2*)&lop[w] = make_uint2(pack_bf2(v.x - h0, v.y - h1),
                                          pack_bf2(v.z - h2, v.w - h3));
        } else {
            Act[r * 65 + c4]     = v.x;
            Act[r * 65 + c4 + 1] = v.y;
            Act[r * 65 + c4 + 2] = v.z;
            Act[r * 65 + c4 + 3] = v.w;
        }
    }

    if (which == 2) {
        __syncthreads();
        const int cchunk = blockIdx.x;
        #pragma unroll
        for (int i = 0; i < 16; i++) {
            int s = tid + i * 256;
            int d = s >> 6, lw = s & 63;
            float f0 = Act[(2 * lw) * 65 + d];
            float f1 = Act[(2 * lw + 1) * 65 + d];
            float h0 = bfr(f0), h1 = bfr(f1);
            int gw = (h * 64 + d) * 1024 + cchunk * 64 + (lw ^ ((d >> 3) & 3));
            g_VThi[gw] = pack_bf2(h0, h1);
            g_VTlo[gw] = pack_bf2(f0 - h0, f1 - h1);
        }
    }
    if (which == 1) {
        float* ksm = (float*)(smem + 73728);
        *(float4*)&ksm[(tid >> 4) * 64 + c4] = make_float4(ksp0, ksp1, ksp2, ksp3);
        __syncthreads();
        if (tid < 64) {
            float s = 0.f;
            #pragma unroll
            for (int g2 = 0; g2 < 16; g2++) s += ksm[g2 * 64 + tid];
            g_stats[(h * NC + blockIdx.x) * STATS_STRIDE + 4096 + tid] = s;
        }
    }
}

// ===========================================================================
// FUSED tail kernel (R14 + deferred St wait): chunk -> prefix -> attn -> out.
// ===========================================================================
#define OFF_QH 0
#define OFF_QL (OFF_QH + 128*36)
#define OFF_KH (OFF_QL + 128*36)
#define OFF_KL (OFF_KH + 128*36)
#define OFF_VH (OFF_KL + 128*36)
#define OFF_VL (OFF_VH + 64*68)
#define OFF_SH (OFF_VL + 64*68)
#define OFF_SL (OFF_SH + 72*36)
#define OFF_AH (OFF_SL + 72*36)
#define OFF_AL (OFF_AH + 128*68)
#define ATTN_SMEM ((OFF_AL + 128*68) * 4)

__global__ void __launch_bounds__(256, 1) fused_tail_kernel(
    const float* __restrict__ bo, float* __restrict__ y)
{
    extern __shared__ uint32_t smw[];

    const int bid = blockIdx.x;
    const int c = bid & 15, h = bid >> 4;
    const int tid = threadIdx.x;
    const uint32_t sbw = smem_u32(smw);
    const int lane = tid & 31, wid = tid >> 5;
    const int lr = lane >> 2, lc = lane & 3;

    // Phase 1: stage VT + Q + K, chunk M = V^T K (trans-ldmatrix B)
    {
        const int vsrc = h * 64 * 1024 + c * 64;
        #pragma unroll
        for (int i = 0; i < 8; i++) {
            int slot = tid + i * 256;
            int p = slot >> 10, d = (slot >> 4) & 63, g = slot & 15;
            cp16(sbw + ((p ? OFF_VL : OFF_VH) + d * 68 + g * 4) * 4,
                 (p ? g_VTlo : g_VThi) + vsrc + d * 1024 + g * 4);
        }
        const int qsrc = (h * T + c * CH) * 32;
        #pragma unroll
        for (int i = 0; i < 8; i++) {
            int slot = tid + i * 256;
            int p = slot >> 10, r = (slot >> 3) & 127, g = slot & 7;
            int so = qsrc + r * 32 + g * 4;
            cp16(sbw + ((p ? OFF_QL : OFF_QH) + r * 36 + g * 4) * 4,
                 (p ? g_Qlo : g_Qhi) + so);
            cp16(sbw + ((p ? OFF_KL : OFF_KH) + r * 36 + g * 4) * 4,
                 (p ? g_Klo : g_Khi) + so);
        }
        CP_COMMIT();
        CP_WAIT0();
        __syncthreads();

        const int wm = (wid & 3) * 16;
        const int wn = (wid >> 2) * 32;
        const int m0 = wm + lr, m1 = m0 + 8;

        uint32_t ah[8][4], al[8][4];
        {
            const int sw0 = (m0 >> 3) & 3;
            const int sw1 = (m1 >> 3) & 3;
            const uint32_t* h0 = smw + OFF_VH + m0 * 68;
            const uint32_t* h1 = smw + OFF_VH + m1 * 68;
            const uint32_t* l0 = smw + OFF_VL + m0 * 68;
            const uint32_t* l1 = smw + OFF_VL + m1 * 68;
            #pragma unroll
            for (int kh = 0; kh < 8; kh++) {
                int w0 = (kh * 8 + lc) ^ sw0;
                int w1 = (kh * 8 + lc) ^ sw1;
                ah[kh][0] = h0[w0];     ah[kh][1] = h1[w1];
                ah[kh][2] = h0[w0 + 4]; ah[kh][3] = h1[w1 + 4];
                al[kh][0] = l0[w0];     al[kh][1] = l1[w1];
                al[kh][2] = l0[w0 + 4]; al[kh][3] = l1[w1 + 4];
            }
        }

        float cb[4][4];
        #pragma unroll
        for (int nt = 0; nt < 4; nt++)
            #pragma unroll
            for (int i = 0; i < 4; i++) cb[nt][i] = 0.f;

        const int trow  = (lane & 7) + 8 * ((lane >> 3) & 1);
        const int tcol8 = 8 * (lane >> 4);
        #pragma unroll
        for (int p = 0; p < 2; p++) {
            const int colb = wn + p * 16 + tcol8;
            #pragma unroll
            for (int kb = 0; kb < 8; kb++) {
                int row = kb * 16 + trow;
                uint32_t aH = sbw + (OFF_KH + row * 36) * 4 + colb * 2;
                uint32_t aL = sbw + (OFF_KL + row * 36) * 4 + colb * 2;
                uint32_t qh4[4], ql4[4];
                ldm_x4_trans(qh4, aH);
                ldm_x4_trans(ql4, aL);
                uint32_t bh0[2] = {qh4[0], qh4[1]}, bh1[2] = {qh4[2], qh4[3]};
                uint32_t bl0[2] = {ql4[0], ql4[1]}, bl1[2] = {ql4[2], ql4[3]};
                mma16(cb[2*p],     ah[kb], bh0);
                mma16(cb[2*p],     al[kb], bh0);
                mma16(cb[2*p],     ah[kb], bl0);
                mma16(cb[2*p + 1], ah[kb], bh1);
                mma16(cb[2*p + 1], al[kb], bh1);
                mma16(cb[2*p + 1], ah[kb], bl1);
            }
        }

        float* outp = g_stats + (h * NC + c) * STATS_STRIDE;
        #pragma unroll
        for (int nt = 0; nt < 4; nt++) {
            int n0 = wn + nt * 8 + 2 * lc;
            *(float2*)&outp[m0 * 64 + n0] = make_float2(cb[nt][0], cb[nt][1]);
            *(float2*)&outp[m1 * 64 + n0] = make_float2(cb[nt][2], cb[nt][3]);
        }
    }

    gsync(0);

    // Phase 2: prefix scan
    if (tid < 144) {
        int slot = bid * 144 + tid;
        int h2 = slot / 2304, s = slot % 2304;
        int row = s >> 5, w = s & 31;

        uint32_t hi[NC], lo[NC];
        if (row < 65) {
            float r0 = 0.f, r1 = 0.f;
            #pragma unroll
            for (int cc = 0; cc < NC; cc++) {
                float h0 = bfr(r0), h1 = bfr(r1);
                hi[cc] = pack_bf2(h0, h1);
                lo[cc] = pack_bf2(r0 - h0, r1 - h1);
                const float* sp = g_stats + (h2 * NC + cc) * STATS_STRIDE;
                if (row < 64) {
                    r0 += sp[row * 64 + 2 * w];
                    r1 += sp[row * 64 + 2 * w + 1];
                } else {
                    r0 += sp[4096 + 2 * w];
                    r1 += sp[4096 + 2 * w + 1];
                }
            }
        } else {
            #pragma unroll
            for (int cc = 0; cc < NC; cc++) { hi[cc] = 0u; lo[cc] = 0u; }
        }
        #pragma unroll
        for (int cc = 0; cc < NC; cc++) {
            int o = ((h2 * NC + cc) * 72 + row) * 32 + w;
            g_Shi[o] = hi[cc];
            g_Slo[o] = lo[cc];
        }
    }

    gsync(1);

    // Phase 3: attention (St staging overlapped with phase A)
    {
        const int ssrc = (h * NC + c) * 72 * 32;
        #pragma unroll
        for (int i = 0; i < 5; i++) {
            int slot = tid + i * 256;
            if (slot < 1152) {
                int p = slot / 576, rem = slot - p * 576, r = rem >> 3, g = rem & 7;
                cp16(sbw + ((p ? OFF_SL : OFF_SH) + r * 36 + g * 4) * 4,
                     (p ? g_Slo : g_Shi) + ssrc + r * 32 + g * 4);
            }
        }
        CP_COMMIT();
        // NOTE: no wait yet — phase A uses only Q/K which are already resident.

        const int wm = wid * 16;
        const int t0 = wm + lr, t1 = t0 + 8;

        uint32_t qh[4][4], ql[4][4];
        {
            const uint32_t* ph = smw + OFF_QH + t0 * 36 + lc;
            const uint32_t* pl = smw + OFF_QL + t0 * 36 + lc;
            #pragma unroll
            for (int kh = 0; kh < 4; kh++) {
                int o = kh * 8;
                qh[kh][0] = ph[o];     qh[kh][1] = ph[o + 288];
                qh[kh][2] = ph[o + 4]; qh[kh][3] = ph[o + 292];
                ql[kh][0] = pl[o];     ql[kh][1] = pl[o + 288];
                ql[kh][2] = pl[o + 4]; ql[kh][3] = pl[o + 292];
            }
        }

        // Phase A: A = Qp Kp^T with causal tile skipping
        float ca[16][4];
        #pragma unroll
        for (int nt = 0; nt < 16; nt++)
            #pragma unroll
            for (int i = 0; i < 4; i++) ca[nt][i] = 0.f;

        const int ntmax = 2 * wid + 1;
        #pragma unroll
        for (int nt = 0; nt < 16; nt++) {
            if (nt <= ntmax) {
                const uint32_t* bhp = smw + OFF_KH + (nt * 8 + lr) * 36 + lc;
                const uint32_t* blp = smw + OFF_KL + (nt * 8 + lr) * 36 + lc;
                #pragma unroll
                for (int kh = 0; kh < 4; kh++) {
                    uint32_t bh[2] = {bhp[kh * 8], bhp[kh * 8 + 4]};
                    uint32_t bl[2] = {blp[kh * 8], blp[kh * 8 + 4]};
                    mma16(ca[nt], qh[kh], bh);
                    mma16(ca[nt], ql[kh], bh);
                    mma16(ca[nt], qh[kh], bl);
                }
            }
        }

        // Mask, rowsum, and build phase-B A-fragments IN REGISTERS.
        float rs0 = 0.f, rs1 = 0.f;
        uint32_t aAh[8][4], aAl[8][4];
        #pragma unroll
        for (int nt = 0; nt < 16; nt++) {
            int s0 = nt * 8 + 2 * lc;
            float c0 = (s0     <= t0) ? ca[nt][0] : 0.f;
            float c1 = (s0 + 1 <= t0) ? ca[nt][1] : 0.f;
            float c2 = (s0     <= t1) ? ca[nt][2] : 0.f;
            float c3 = (s0 + 1 <= t1) ? ca[nt][3] : 0.f;
            rs0 += c0 + c1;
            rs1 += c2 + c3;
            float h0 = bfr(c0), h1 = bfr(c1), h2 = bfr(c2), h3 = bfr(c3);
            int kb = nt >> 1, half = nt & 1;
            aAh[kb][half * 2 + 0] = pack_bf2(h0, h1);
            aAh[kb][half * 2 + 1] = pack_bf2(h2, h3);
            aAl[kb][half * 2 + 0] = pack_bf2(c0 - h0, c1 - h1);
            aAl[kb][half * 2 + 1] = pack_bf2(c2 - h2, c3 - h3);
        }
        rs0 += __shfl_xor_sync(0xffffffffu, rs0, 1);
        rs0 += __shfl_xor_sync(0xffffffffu, rs0, 2);
        rs1 += __shfl_xor_sync(0xffffffffu, rs1, 1);
        rs1 += __shfl_xor_sync(0xffffffffu, rs1, 2);

        // Now wait for St (latency hidden behind phase A).
        CP_WAIT0();
        __syncthreads();

        // Phase B
        float cb[9][4];
        #pragma unroll
        for (int nt = 0; nt < 9; nt++)
            #pragma unroll
            for (int i = 0; i < 4; i++) cb[nt][i] = 0.f;

        #pragma unroll
        for (int nt = 0; nt < 8; nt++) {
            int n = nt * 8 + lr;
            int swB = nt & 3;
            const uint32_t* vh = smw + OFF_VH + n * 68;
            const uint32_t* vl = smw + OFF_VL + n * 68;
            #pragma unroll
            for (int kh = 0; kh < 8; kh++) {
                if (kh <= wid) {
                    int w = (kh * 8 + lc) ^ swB;
                    uint32_t bh[2] = {vh[w], vh[w + 4]};
                    uint32_t bl[2] = {vl[w], vl[w + 4]};
                    mma16(cb[nt], aAh[kh], bh);
                    mma16(cb[nt], aAl[kh], bh);
                    mma16(cb[nt], aAh[kh], bl);
                }
            }
            const uint32_t* sh = smw + OFF_SH + n * 36 + lc;
            const uint32_t* sl = smw + OFF_SL + n * 36 + lc;
            #pragma unroll
            for (int ks = 0; ks < 4; ks++) {
                uint32_t bh[2] = {sh[ks * 8], sh[ks * 8 + 4]};
                uint32_t bl[2] = {sl[ks * 8], sl[ks * 8 + 4]};
                mma16(cb[nt], qh[ks], bh);
                mma16(cb[nt], ql[ks], bh);
                mma16(cb[nt], qh[ks], bl);
            }
        }
        {
            int n = 64 + lr;
            const uint32_t* sh = smw + OFF_SH + n * 36 + lc;
            const uint32_t* sl = smw + OFF_SL + n * 36 + lc;
            #pragma unroll
            for (int ks = 0; ks < 4; ks++) {
                uint32_t bh[2] = {sh[ks * 8], sh[ks * 8 + 4]};
                uint32_t bl[2] = {sl[ks * 8], sl[ks * 8 + 4]};
                mma16(cb[8], qh[ks], bh);
                mma16(cb[8], ql[ks], bh);
                mma16(cb[8], qh[ks], bl);
            }
        }

        float di0 = __shfl_sync(0xffffffffu, cb[8][0], lane & ~3);
        float di1 = __shfl_sync(0xffffffffu, cb[8][2], lane & ~3);
        float inv0 = 1.f / fmaxf(rs0 + di0, 1e-6f);
        float inv1 = 1.f / fmaxf(rs1 + di1, 1e-6f);

        const int base = (c * CH) * (Dm / 2) + h * 32;
        #pragma unroll
        for (int nt = 0; nt < 8; nt++) {
            int jw = (nt * 8 + 2 * lc) >> 1;
            {
                float o0 = cb[nt][0] * inv0, o1 = cb[nt][1] * inv0;
                float h0 = bfr(o0), h1 = bfr(o1);
                g_Ohi[base + t0 * (Dm / 2) + jw] = pack_bf2(h0, h1);
                g_Olo[base + t0 * (Dm / 2) + jw] = pack_bf2(o0 - h0, o1 - h1);
            }
            {
                float o0 = cb[nt][2] * inv1, o1 = cb[nt][3] * inv1;
                float h0 = bfr(o0), h1 = bfr(o1);
                g_Ohi[base + t1 * (Dm / 2) + jw] = pack_bf2(h0, h1);
                g_Olo[base + t1 * (Dm / 2) + jw] = pack_bf2(o0 - h0, o1 - h1);
            }
        }
    }

    gsync(2);

    // Phase 4: output projection
    {
        const int row0 = (bid & 15) * 128;
        const int col0 = (bid >> 4) * 64;

        float acc[2][4][4];
        gemm_tc((char*)smw, (const char*)g_Ohi, (const char*)g_Olo,
                (const char*)(g_whi + 3 * (Dm * Dm / 2)),
                (const char*)(g_wlo + 3 * (Dm * Dm / 2)),
                row0, col0, acc);

        float* Cs = (float*)smw;
        acc_to_smem(Cs, acc);
        __syncthreads();

        #pragma unroll
        for (int it = 0; it < 8; it++) {
            int idx = tid + it * 256;
            int r = idx >> 4, c4 = (idx & 15) << 2;
            float4 v = *(float4*)&Cs[r * C_STR + c4];
            v.x += bo[col0 + c4 + 0];
            v.y += bo[col0 + c4 + 1];
            v.z += bo[col0 + c4 + 2];
            v.w += bo[col0 + c4 + 3];
            *(float4*)&y[(row0 + r) * Dm + col0 + c4] = v;
        }
    }
}

// ---------------------------------------------------------------------------
extern "C" void kernel_launch(void* const* d_in, const int* in_sizes, int n_in,
                              void* d_out, int out_size)
{
    const float* x  = (const float*)d_in[0];
    const float* Wq = (const float*)d_in[1];
    const float* bq = (const float*)d_in[2];
    const float* Wk = (const float*)d_in[3];
    const float* bk = (const float*)d_in[4];
    const float* Wv = (const float*)d_in[5];
    const float* bv = (const float*)d_in[6];
    const float* Wo = (const float*)d_in[7];
    const float* bo = (const float*)d_in[8];
    float* y = (float*)d_out;

    cudaFuncSetAttribute(qkv_tc_kernel,
                         cudaFuncAttributeMaxDynamicSharedMemorySize, GEMM_SMEM);
    cudaFuncSetAttribute(fused_tail_kernel,
                         cudaFuncAttributeMaxDynamicSharedMemorySize, ATTN_SMEM);

    prep_kernel      <<<dim3(16, 16, 5), 256>>>(x, Wq, Wk, Wv, Wo);
    qkv_tc_kernel    <<<dim3(T/128, H, 3), 256, GEMM_SMEM>>>(bq, bk, bv);
    fused_tail_kernel<<<128, 256, ATTN_SMEM>>>(bo, y);
}

// round 17
// speedup vs baseline: 1.5405x; 1.0258x over previous
#include <cuda_runtime.h>
#include <cuda_bf16.h>
#include <math.h>
#include <stdint.h>

// Problem constants
#define T   2048
#define Dm  512
#define H   8
#define DH  64
#define CH  128
#define NC  (T / CH)
#define STATS_STRIDE (DH*DH + DH)   // 4160

// Scratch (device globals — no allocation allowed)
__device__ float g_stats[H * NC * STATS_STRIDE];   // KV^T [j*64+i]; ksum @4096 (by qkv)
__device__ unsigned g_syncc[4];                    // monotonic grid barriers
// Pre-split bf16 planes (packed uint32 = 2 bf16)
__device__ uint32_t g_xhi[T * Dm / 2], g_xlo[T * Dm / 2];           // x row-major [t][k]
__device__ uint32_t g_whi[4 * Dm * Dm / 2], g_wlo[4 * Dm * Dm / 2]; // W^T [m][n][k]
__device__ uint32_t g_Qhi[H * T * 32], g_Qlo[H * T * 32];           // Qp row-major
__device__ uint32_t g_Khi[H * T * 32], g_Klo[H * T * 32];           // Kp row-major
__device__ uint32_t g_VThi[H * 64 * 1024], g_VTlo[H * 64 * 1024];   // V^T, swizzled
__device__ uint32_t g_Shi[H * NC * 72 * 32], g_Slo[H * NC * 72 * 32]; // St planes
__device__ uint32_t g_Ohi[T * Dm / 2], g_Olo[T * Dm / 2];           // attn out [t][n]

// ===========================================================================
// Helpers
// ===========================================================================
__device__ __forceinline__ uint32_t pack_bf2(float a, float b) {
    __nv_bfloat162 t;
    t.x = __float2bfloat16_rn(a);
    t.y = __float2bfloat16_rn(b);
    return *(uint32_t*)&t;
}
__device__ __forceinline__ float bfr(float x) {
    return __bfloat162float(__float2bfloat16_rn(x));
}
__device__ __forceinline__ void mma16(float c[4], const uint32_t a[4], const uint32_t b[2]) {
    asm volatile(
        "mma.sync.aligned.m16n8k16.row.col.f32.bf16.bf16.f32 "
        "{%0,%1,%2,%3}, {%4,%5,%6,%7}, {%8,%9}, {%0,%1,%2,%3};"
        : "+f"(c[0]), "+f"(c[1]), "+f"(c[2]), "+f"(c[3])
        : "r"(a[0]), "r"(a[1]), "r"(a[2]), "r"(a[3]),
          "r"(b[0]), "r"(b[1]));
}
__device__ __forceinline__ uint32_t smem_u32(const void* p) {
    uint32_t a;
    asm("{ .reg .u64 t; cvta.to.shared.u64 t, %1; cvt.u32.u64 %0, t; }"
        : "=r"(a) : "l"(p));
    return a;
}
__device__ __forceinline__ void ldm_x4(uint32_t* r, uint32_t addr) {
    asm volatile("ldmatrix.sync.aligned.m8n8.x4.shared.b16 {%0,%1,%2,%3}, [%4];"
        : "=r"(r[0]), "=r"(r[1]), "=r"(r[2]), "=r"(r[3]) : "r"(addr));
}
__device__ __forceinline__ void ldm_x4_trans(uint32_t* r, uint32_t addr) {
    asm volatile("ldmatrix.sync.aligned.m8n8.x4.trans.shared.b16 {%0,%1,%2,%3}, [%4];"
        : "=r"(r[0]), "=r"(r[1]), "=r"(r[2]), "=r"(r[3]) : "r"(addr));
}
__device__ __forceinline__ void cp16(uint32_t dst, const void* src) {
    asm volatile("cp.async.cg.shared.global [%0], [%1], 16;" :: "r"(dst), "l"(src));
}
#define CP_COMMIT() asm volatile("cp.async.commit_group;" ::: "memory")
#define CP_WAIT0()  asm volatile("cp.async.wait_group 0;" ::: "memory")

// Grid barrier: monotonic counter (graph-replay safe; 128 CTAs all resident).
__device__ __forceinline__ void gsync(int k) {
    __syncthreads();
    if (threadIdx.x == 0) {
        __threadfence();
        unsigned old = atomicAdd(&g_syncc[k], 1u);
        unsigned target = (old & ~127u) + 128u;
        while (atomicAdd(&g_syncc[k], 0u) < target) { }
        __threadfence();
    }
    __syncthreads();
}

// ===========================================================================
// Prep kernel: split W (transposed) + x into bf16 hi/lo planes. grid (16,16,5)
// ===========================================================================
__global__ void prep_kernel(const float* __restrict__ x,
                            const float* __restrict__ Wq, const float* __restrict__ Wk,
                            const float* __restrict__ Wv, const float* __restrict__ Wo)
{
    if (blockIdx.z < 4) {
        __shared__ float tile[32][33];
        const int m = blockIdx.z;
        const float* W = (m == 0) ? Wq : (m == 1) ? Wk : (m == 2) ? Wv : Wo;
        const int kb = blockIdx.x * 32, nb = blockIdx.y * 32;
        const int tid = threadIdx.x;
        const int tr = tid >> 5, tc = tid & 31;
        #pragma unroll
        for (int i = 0; i < 4; i++)
            tile[tr + i * 8][tc] = W[(kb + tr + i * 8) * Dm + nb + tc];
        __syncthreads();
        const int nr = tid >> 4, k2 = (tid & 15) * 2;
        #pragma unroll
        for (int i = 0; i < 2; i++) {
            int n = nr + i * 16;
            float v0 = tile[k2][n], v1 = tile[k2 + 1][n];
            float h0 = bfr(v0), h1 = bfr(v1);
            int widx = m * (Dm * Dm / 2) + (nb + n) * (Dm / 2) + ((kb + k2) >> 1);
            g_whi[widx] = pack_bf2(h0, h1);
            g_wlo[widx] = pack_bf2(v0 - h0, v1 - h1);
        }
    } else {
        int base = (blockIdx.y * 16 + blockIdx.x) * 256 + threadIdx.x;
        #pragma unroll
        for (int k = 0; k < 4; k++) {
            int idx = base + k * 65536;
            float4 v = ((const float4*)x)[idx];
            float h0 = bfr(v.x), h1 = bfr(v.y), h2 = bfr(v.z), h3 = bfr(v.w);
            ((uint2*)g_xhi)[idx] = make_uint2(pack_bf2(h0, h1), pack_bf2(h2, h3));
            ((uint2*)g_xlo)[idx] = make_uint2(pack_bf2(v.x - h0, v.y - h1),
                                              pack_bf2(v.z - h2, v.w - h3));
        }
    }
}

// ===========================================================================
// Shared GEMM pieces
// ===========================================================================
#define GB_BUF 49152
#define GEMM_SMEM 98304
#define C_STR 68

__device__ __forceinline__ void acc_to_smem(float* Cs, const float acc[2][4][4])
{
    const int lane = threadIdx.x & 31;
    const int wid  = threadIdx.x >> 5;
    const int wm   = (wid & 3) * 32;
    const int wn   = (wid >> 2) * 32;
    const int lr = lane >> 2, lc = lane & 3;

    #pragma unroll
    for (int mt = 0; mt < 2; mt++)
        #pragma unroll
        for (int nt = 0; nt < 4; nt++) {
            int r = wm + mt * 16 + lr;
            int n = wn + nt * 8 + 2 * lc;
            #pragma unroll
            for (int i = 0; i < 4; i++)
                Cs[(r + (i >= 2 ? 8 : 0)) * C_STR + n + (i & 1)] = acc[mt][nt][i];
        }
}

// BK=64 GEMM for the output projection (unchanged from R14)
__device__ __forceinline__ void gemm_tc(char* smem,
    const char* Ahi, const char* Alo, const char* Bhi, const char* Blo,
    int row0, int col0, float acc[2][4][4])
{
    const int tid = threadIdx.x, lane = tid & 31, wid = tid >> 5;
    const int wm = (wid & 3) * 32, wn = (wid >> 2) * 32;
    uint32_t sb = smem_u32(smem);

    #pragma unroll
    for (int mt = 0; mt < 2; mt++)
        #pragma unroll
        for (int nt = 0; nt < 4; nt++)
            #pragma unroll
            for (int i = 0; i < 4; i++) acc[mt][nt][i] = 0.f;

    uint32_t smA[8]; const char* gA[8];
    #pragma unroll
    for (int i = 0; i < 8; i++) {
        int c = tid + i * 256;
        int plane = c >> 10, rc = c & 1023, r = rc >> 3, g = rc & 7;
        smA[i] = plane * 16384 + r * 128 + ((g ^ (r & 7)) << 4);
        gA[i] = (plane ? Alo : Ahi) + (size_t)(row0 + r) * 1024 + g * 16;
    }
    uint32_t smB[4]; const char* gB[4];
    #pragma unroll
    for (int i = 0; i < 4; i++) {
        int c = tid + i * 256;
        int plane = c >> 9, rc = c & 511, n = rc >> 3, g = rc & 7;
        smB[i] = 32768 + plane * 8192 + n * 128 + ((g ^ (n & 7)) << 4);
        gB[i] = (plane ? Blo : Bhi) + (size_t)(col0 + n) * 1024 + g * 16;
    }

    #pragma unroll
    for (int i = 0; i < 8; i++) cp16(sb + smA[i], gA[i]);
    #pragma unroll
    for (int i = 0; i < 4; i++) cp16(sb + smB[i], gB[i]);
    CP_COMMIT();

    const int rA = wm + (lane & 15);
    const int nB = wn + (lane & 15);
    const int seg = lane >> 4;
    const int xv = lane & 7;

    for (int s = 0; s < 8; s++) {
        CP_WAIT0();
        __syncthreads();
        if (s + 1 < 8) {
            int koff = (s + 1) * 128;
            uint32_t boff = (uint32_t)(((s + 1) & 1) * GB_BUF);
            #pragma unroll
            for (int i = 0; i < 8; i++) cp16(sb + boff + smA[i], gA[i] + koff);
            #pragma unroll
            for (int i = 0; i < 4; i++) cp16(sb + boff + smB[i], gB[i] + koff);
            CP_COMMIT();
        }
        uint32_t bufb = sb + (uint32_t)((s & 1) * GB_BUF);

        #pragma unroll
        for (int ks = 0; ks < 4; ks++) {
            uint32_t sw = (uint32_t)((((ks << 1) + seg) ^ xv) << 4);
            uint32_t ah[2][4], al[2][4];
            {
                uint32_t a0 = bufb + rA * 128 + sw;
                ldm_x4(ah[0], a0);
                ldm_x4(al[0], a0 + 16384);
                uint32_t a1 = a0 + 16 * 128;
                ldm_x4(ah[1], a1);
                ldm_x4(al[1], a1 + 16384);
            }
            uint32_t q[4], bh[4][2], bl[4][2];
            {
                uint32_t b0 = bufb + 32768 + nB * 128 + sw;
                ldm_x4(q, b0);
                bh[0][0] = q[0]; bh[0][1] = q[2]; bh[1][0] = q[1]; bh[1][1] = q[3];
                ldm_x4(q, b0 + 8192);
                bl[0][0] = q[0]; bl[0][1] = q[2]; bl[1][0] = q[1]; bl[1][1] = q[3];
                uint32_t b1 = b0 + 16 * 128;
                ldm_x4(q, b1);
                bh[2][0] = q[0]; bh[2][1] = q[2]; bh[3][0] = q[1]; bh[3][1] = q[3];
                ldm_x4(q, b1 + 8192);
                bl[2][0] = q[0]; bl[2][1] = q[2]; bl[3][0] = q[1]; bl[3][1] = q[3];
            }
            #pragma unroll
            for (int mt = 0; mt < 2; mt++)
                #pragma unroll
                for (int nt = 0; nt < 4; nt++) {
                    mma16(acc[mt][nt], ah[mt], bh[nt]);
                    mma16(acc[mt][nt], al[mt], bh[nt]);
                    mma16(acc[mt][nt], ah[mt], bl[nt]);
                }
        }
    }
}

// ===========================================================================
// Kernel 1: TRIPLE-fused QKV projection — one CTA does Q,K,V for its
// (row-tile, head): A slab staged ONCE per K-step, 3 B blocks.
// grid = (T/128, H) = 128 CTAs. smem: 2 x (A 32K + 3xB 16K) = 160KB.
// ===========================================================================
#define Q3_BUF  81920
#define Q3_SMEM 163840
#define WSTRIDE 524288           // bytes between W matrices in g_whi/g_wlo

__device__ __forceinline__ void qkv_epilogue(int which, const float acc[2][4][4],
                                             const float* __restrict__ b,
                                             int row0, int h, int cchunk, char* smem)
{
    float* Cs = (float*)smem;
    acc_to_smem(Cs, acc);
    __syncthreads();

    const int tid = threadIdx.x;
    const int col0 = h * 64;
    float* Act = (float*)(smem + 36864);
    const int c4 = (tid & 15) << 2;
    float ksp0 = 0.f, ksp1 = 0.f, ksp2 = 0.f, ksp3 = 0.f;
    const float bb0 = b[col0 + c4], bb1 = b[col0 + c4 + 1];
    const float bb2 = b[col0 + c4 + 2], bb3 = b[col0 + c4 + 3];

    #pragma unroll
    for (int it = 0; it < 8; it++) {
        int r = (tid >> 4) + it * 16;
        float4 v = *(float4*)&Cs[r * C_STR + c4];
        v.x += bb0; v.y += bb1; v.z += bb2; v.w += bb3;
        if (which < 2) {
            v.x = (v.x > 0.f) ? (v.x + 1.f) : __expf(v.x);
            v.y = (v.y > 0.f) ? (v.y + 1.f) : __expf(v.y);
            v.z = (v.z > 0.f) ? (v.z + 1.f) : __expf(v.z);
            v.w = (v.w > 0.f) ? (v.w + 1.f) : __expf(v.w);
        }
        if (which == 1) { ksp0 += v.x; ksp1 += v.y; ksp2 += v.z; ksp3 += v.w; }
        if (which < 2) {
            float h0 = bfr(v.x), h1 = bfr(v.y), h2 = bfr(v.z), h3 = bfr(v.w);
            uint32_t* hip = which ? g_Khi : g_Qhi;
            uint32_t* lop = which ? g_Klo : g_Qlo;
            int w = (h * T + row0 + r) * 32 + (c4 >> 1);
            *(uint2*)&hip[w] = make_uint2(pack_bf2(h0, h1), pack_bf2(h2, h3));
            *(uint2*)&lop[w] = make_uint2(pack_bf2(v.x - h0, v.y - h1),
                                          pack_bf2(v.z - h2, v.w - h3));
        } else {
            Act[r * 65 + c4]     = v.x;
            Act[r * 65 + c4 + 1] = v.y;
            Act[r * 65 + c4 + 2] = v.z;
            Act[r * 65 + c4 + 3] = v.w;
        }
    }

    if (which == 2) {
        __syncthreads();
        #pragma unroll
        for (int i = 0; i < 16; i++) {
            int s = tid + i * 256;
            int d = s >> 6, lw = s & 63;
            float f0 = Act[(2 * lw) * 65 + d];
            float f1 = Act[(2 * lw + 1) * 65 + d];
            float h0 = bfr(f0), h1 = bfr(f1);
            int gw = (h * 64 + d) * 1024 + cchunk * 64 + (lw ^ ((d >> 3) & 3));
            g_VThi[gw] = pack_bf2(h0, h1);
            g_VTlo[gw] = pack_bf2(f0 - h0, f1 - h1);
        }
    }
    if (which == 1) {
        float* ksm = (float*)(smem + 73728);
        *(float4*)&ksm[(tid >> 4) * 64 + c4] = make_float4(ksp0, ksp1, ksp2, ksp3);
        __syncthreads();
        if (tid < 64) {
            float s = 0.f;
            #pragma unroll
            for (int g2 = 0; g2 < 16; g2++) s += ksm[g2 * 64 + tid];
            g_stats[(h * NC + cchunk) * STATS_STRIDE + 4096 + tid] = s;
        }
    }
    __syncthreads();   // Cs/Act reused by next which
}

__global__ void __launch_bounds__(256, 1) qkv3_kernel(
    const float* __restrict__ bq, const float* __restrict__ bk,
    const float* __restrict__ bv)
{
    extern __shared__ char smem[];
    uint32_t sb = smem_u32(smem);

    const int tid = threadIdx.x, lane = tid & 31, wid = tid >> 5;
    const int wm = (wid & 3) * 32, wn = (wid >> 2) * 32;
    const int row0 = blockIdx.x * 128;
    const int h    = blockIdx.y;
    const int col0 = h * 64;

    float accQ[2][4][4], accK[2][4][4], accV[2][4][4];
    #pragma unroll
    for (int mt = 0; mt < 2; mt++)
        #pragma unroll
        for (int nt = 0; nt < 4; nt++)
            #pragma unroll
            for (int i = 0; i < 4; i++) {
                accQ[mt][nt][i] = 0.f; accK[mt][nt][i] = 0.f; accV[mt][nt][i] = 0.f;
            }

    uint32_t smA[8]; const char* gA[8];
    #pragma unroll
    for (int i = 0; i < 8; i++) {
        int c = tid + i * 256;
        int plane = c >> 10, rc = c & 1023, r = rc >> 3, g = rc & 7;
        smA[i] = plane * 16384 + r * 128 + ((g ^ (r & 7)) << 4);
        gA[i] = (const char*)(plane ? g_xlo : g_xhi) + (size_t)(row0 + r) * 1024 + g * 16;
    }
    uint32_t smB[4]; const char* gB[4];
    #pragma unroll
    for (int i = 0; i < 4; i++) {
        int c = tid + i * 256;
        int plane = c >> 9, rc = c & 511, n = rc >> 3, g = rc & 7;
        smB[i] = 32768 + plane * 8192 + n * 128 + ((g ^ (n & 7)) << 4);
        gB[i] = (const char*)(plane ? g_wlo : g_whi) + (size_t)(col0 + n) * 1024 + g * 16;
    }

    // prologue: slab 0 (A once, B x3 matrices)
    #pragma unroll
    for (int i = 0; i < 8; i++) cp16(sb + smA[i], gA[i]);
    #pragma unroll
    for (int m = 0; m < 3; m++)
        #pragma unroll
        for (int i = 0; i < 4; i++)
            cp16(sb + smB[i] + m * 16384, gB[i] + (size_t)m * WSTRIDE);
    CP_COMMIT();

    const int rA = wm + (lane & 15);
    const int nB = wn + (lane & 15);
    const int seg = lane >> 4;
    const int xv = lane & 7;

    for (int s = 0; s < 8; s++) {
        CP_WAIT0();
        __syncthreads();
        if (s + 1 < 8) {
            int koff = (s + 1) * 128;
            uint32_t boff = (uint32_t)(((s + 1) & 1) * Q3_BUF);
            #pragma unroll
            for (int i = 0; i < 8; i++) cp16(sb + boff + smA[i], gA[i] + koff);
            #pragma unroll
            for (int m = 0; m < 3; m++)
                #pragma unroll
                for (int i = 0; i < 4; i++)
                    cp16(sb + boff + smB[i] + m * 16384,
                         gB[i] + (size_t)m * WSTRIDE + koff);
            CP_COMMIT();
        }
        uint32_t bufb = sb + (uint32_t)((s & 1) * Q3_BUF);

        #pragma unroll
        for (int ks = 0; ks < 4; ks++) {
            uint32_t sw = (uint32_t)((((ks << 1) + seg) ^ xv) << 4);
            uint32_t ah[2][4], al[2][4];
            {
                uint32_t a0 = bufb + rA * 128 + sw;
                ldm_x4(ah[0], a0);
                ldm_x4(al[0], a0 + 16384);
                uint32_t a1 = a0 + 16 * 128;
                ldm_x4(ah[1], a1);
                ldm_x4(al[1], a1 + 16384);
            }
#define Q3_MAT(ACC, MOFF) { \
            uint32_t q[4], bh[4][2], bl[4][2]; \
            uint32_t b0 = bufb + 32768 + (MOFF) + nB * 128 + sw; \
            ldm_x4(q, b0); \
            bh[0][0] = q[0]; bh[0][1] = q[2]; bh[1][0] = q[1]; bh[1][1] = q[3]; \
            ldm_x4(q, b0 + 8192); \
            bl[0][0] = q[0]; bl[0][1] = q[2]; bl[1][0] = q[1]; bl[1][1] = q[3]; \
            uint32_t b1 = b0 + 16 * 128; \
            ldm_x4(q, b1); \
            bh[2][0] = q[0]; bh[2][1] = q[2]; bh[3][0] = q[1]; bh[3][1] = q[3]; \
            ldm_x4(q, b1 + 8192); \
            bl[2][0] = q[0]; bl[2][1] = q[2]; bl[3][0] = q[1]; bl[3][1] = q[3]; \
            _Pragma("unroll") \
            for (int mt = 0; mt < 2; mt++) \
                _Pragma("unroll") \
                for (int nt = 0; nt < 4; nt++) { \
                    mma16(ACC[mt][nt], ah[mt], bh[nt]); \
                    mma16(ACC[mt][nt], al[mt], bh[nt]); \
                    mma16(ACC[mt][nt], ah[mt], bl[nt]); \
                } }
            Q3_MAT(accQ, 0)
            Q3_MAT(accK, 16384)
            Q3_MAT(accV, 32768)
#undef Q3_MAT
        }
    }
    __syncthreads();

    qkv_epilogue(0, accQ, bq, row0, h, blockIdx.x, smem);
    qkv_epilogue(1, accK, bk, row0, h, blockIdx.x, smem);
    qkv_epilogue(2, accV, bv, row0, h, blockIdx.x, smem);
}

// ===========================================================================
// FUSED tail kernel (R14, verbatim): chunk -> prefix -> attn -> out.
// ===========================================================================
#define OFF_QH 0
#define OFF_QL (OFF_QH + 128*36)
#define OFF_KH (OFF_QL + 128*36)
#define OFF_KL (OFF_KH + 128*36)
#define OFF_VH (OFF_KL + 128*36)
#define OFF_VL (OFF_VH + 64*68)
#define OFF_SH (OFF_VL + 64*68)
#define OFF_SL (OFF_SH + 72*36)
#define OFF_AH (OFF_SL + 72*36)
#define OFF_AL (OFF_AH + 128*68)
#define ATTN_SMEM ((OFF_AL + 128*68) * 4)

__global__ void __launch_bounds__(256, 1) fused_tail_kernel(
    const float* __restrict__ bo, float* __restrict__ y)
{
    extern __shared__ uint32_t smw[];

    const int bid = blockIdx.x;
    const int c = bid & 15, h = bid >> 4;
    const int tid = threadIdx.x;
    const uint32_t sbw = smem_u32(smw);
    const int lane = tid & 31, wid = tid >> 5;
    const int lr = lane >> 2, lc = lane & 3;

    // Phase 1: stage VT + Q + K, chunk M = V^T K (trans-ldmatrix B)
    {
        const int vsrc = h * 64 * 1024 + c * 64;
        #pragma unroll
        for (int i = 0; i < 8; i++) {
            int slot = tid + i * 256;
            int p = slot >> 10, d = (slot >> 4) & 63, g = slot & 15;
            cp16(sbw + ((p ? OFF_VL : OFF_VH) + d * 68 + g * 4) * 4,
                 (p ? g_VTlo : g_VThi) + vsrc + d * 1024 + g * 4);
        }
        const int qsrc = (h * T + c * CH) * 32;
        #pragma unroll
        for (int i = 0; i < 8; i++) {
            int slot = tid + i * 256;
            int p = slot >> 10, r = (slot >> 3) & 127, g = slot & 7;
            int so = qsrc + r * 32 + g * 4;
            cp16(sbw + ((p ? OFF_QL : OFF_QH) + r * 36 + g * 4) * 4,
                 (p ? g_Qlo : g_Qhi) + so);
            cp16(sbw + ((p ? OFF_KL : OFF_KH) + r * 36 + g * 4) * 4,
                 (p ? g_Klo : g_Khi) + so);
        }
        CP_COMMIT();
        CP_WAIT0();
        __syncthreads();

        const int wm = (wid & 3) * 16;
        const int wn = (wid >> 2) * 32;
        const int m0 = wm + lr, m1 = m0 + 8;

        uint32_t ah[8][4], al[8][4];
        {
            const int sw0 = (m0 >> 3) & 3;
            const int sw1 = (m1 >> 3) & 3;
            const uint32_t* h0 = smw + OFF_VH + m0 * 68;
            const uint32_t* h1 = smw + OFF_VH + m1 * 68;
            const uint32_t* l0 = smw + OFF_VL + m0 * 68;
            const uint32_t* l1 = smw + OFF_VL + m1 * 68;
            #pragma unroll
            for (int kh = 0; kh < 8; kh++) {
                int w0 = (kh * 8 + lc) ^ sw0;
                int w1 = (kh * 8 + lc) ^ sw1;
                ah[kh][0] = h0[w0];     ah[kh][1] = h1[w1];
                ah[kh][2] = h0[w0 + 4]; ah[kh][3] = h1[w1 + 4];
                al[kh][0] = l0[w0];     al[kh][1] = l1[w1];
                al[kh][2] = l0[w0 + 4]; al[kh][3] = l1[w1 + 4];
            }
        }

        float cb[4][4];
        #pragma unroll
        for (int nt = 0; nt < 4; nt++)
            #pragma unroll
            for (int i = 0; i < 4; i++) cb[nt][i] = 0.f;

        const int trow  = (lane & 7) + 8 * ((lane >> 3) & 1);
        const int tcol8 = 8 * (lane >> 4);
        #pragma unroll
        for (int p = 0; p < 2; p++) {
            const int colb = wn + p * 16 + tcol8;
            #pragma unroll
            for (int kb = 0; kb < 8; kb++) {
                int row = kb * 16 + trow;
                uint32_t aH = sbw + (OFF_KH + row * 36) * 4 + colb * 2;
                uint32_t aL = sbw + (OFF_KL + row * 36) * 4 + colb * 2;
                uint32_t qh4[4], ql4[4];
                ldm_x4_trans(qh4, aH);
                ldm_x4_trans(ql4, aL);
                uint32_t bh0[2] = {qh4[0], qh4[1]}, bh1[2] = {qh4[2], qh4[3]};
                uint32_t bl0[2] = {ql4[0], ql4[1]}, bl1[2] = {ql4[2], ql4[3]};
                mma16(cb[2*p],     ah[kb], bh0);
                mma16(cb[2*p],     al[kb], bh0);
                mma16(cb[2*p],     ah[kb], bl0);
                mma16(cb[2*p + 1], ah[kb], bh1);
                mma16(cb[2*p + 1], al[kb], bh1);
                mma16(cb[2*p + 1], ah[kb], bl1);
            }
        }

        float* outp = g_stats + (h * NC + c) * STATS_STRIDE;
        #pragma unroll
        for (int nt = 0; nt < 4; nt++) {
            int n0 = wn + nt * 8 + 2 * lc;
            *(float2*)&outp[m0 * 64 + n0] = make_float2(cb[nt][0], cb[nt][1]);
            *(float2*)&outp[m1 * 64 + n0] = make_float2(cb[nt][2], cb[nt][3]);
        }
    }

    gsync(0);

    // Phase 2: prefix scan
    if (tid < 144) {
        int slot = bid * 144 + tid;
        int h2 = slot / 2304, s = slot % 2304;
        int row = s >> 5, w = s & 31;

        uint32_t hi[NC], lo[NC];
        if (row < 65) {
            float r0 = 0.f, r1 = 0.f;
            #pragma unroll
            for (int cc = 0; cc < NC; cc++) {
                float h0 = bfr(r0), h1 = bfr(r1);
                hi[cc] = pack_bf2(h0, h1);
                lo[cc] = pack_bf2(r0 - h0, r1 - h1);
                const float* sp = g_stats + (h2 * NC + cc) * STATS_STRIDE;
                if (row < 64) {
                    r0 += sp[row * 64 + 2 * w];
                    r1 += sp[row * 64 + 2 * w + 1];
                } else {
                    r0 += sp[4096 + 2 * w];
                    r1 += sp[4096 + 2 * w + 1];
                }
            }
        } else {
            #pragma unroll
            for (int cc = 0; cc < NC; cc++) { hi[cc] = 0u; lo[cc] = 0u; }
        }
        #pragma unroll
        for (int cc = 0; cc < NC; cc++) {
            int o = ((h2 * NC + cc) * 72 + row) * 32 + w;
            g_Shi[o] = hi[cc];
            g_Slo[o] = lo[cc];
        }
    }

    gsync(1);

    // Phase 3: attention (A-fragments built in registers)
    {
        const int ssrc = (h * NC + c) * 72 * 32;
        #pragma unroll
        for (int i = 0; i < 5; i++) {
            int slot = tid + i * 256;
            if (slot < 1152) {
                int p = slot / 576, rem = slot - p * 576, r = rem >> 3, g = rem & 7;
                cp16(sbw + ((p ? OFF_SL : OFF_SH) + r * 36 + g * 4) * 4,
                     (p ? g_Slo : g_Shi) + ssrc + r * 32 + g * 4);
            }
        }
        CP_COMMIT();
        CP_WAIT0();
        __syncthreads();

        const int wm = wid * 16;
        const int t0 = wm + lr, t1 = t0 + 8;

        uint32_t qh[4][4], ql[4][4];
        {
            const uint32_t* ph = smw + OFF_QH + t0 * 36 + lc;
            const uint32_t* pl = smw + OFF_QL + t0 * 36 + lc;
            #pragma unroll
            for (int kh = 0; kh < 4; kh++) {
                int o = kh * 8;
                qh[kh][0] = ph[o];     qh[kh][1] = ph[o + 288];
                qh[kh][2] = ph[o + 4]; qh[kh][3] = ph[o + 292];
                ql[kh][0] = pl[o];     ql[kh][1] = pl[o + 288];
                ql[kh][2] = pl[o + 4]; ql[kh][3] = pl[o + 292];
            }
        }

        float ca[16][4];
        #pragma unroll
        for (int nt = 0; nt < 16; nt++)
            #pragma unroll
            for (int i = 0; i < 4; i++) ca[nt][i] = 0.f;

        const int ntmax = 2 * wid + 1;
        #pragma unroll
        for (int nt = 0; nt < 16; nt++) {
            if (nt <= ntmax) {
                const uint32_t* bhp = smw + OFF_KH + (nt * 8 + lr) * 36 + lc;
                const uint32_t* blp = smw + OFF_KL + (nt * 8 + lr) * 36 + lc;
                #pragma unroll
                for (int kh = 0; kh < 4; kh++) {
                    uint32_t bh[2] = {bhp[kh * 8], bhp[kh * 8 + 4]};
                    uint32_t bl[2] = {blp[kh * 8], blp[kh * 8 + 4]};
                    mma16(ca[nt], qh[kh], bh);
                    mma16(ca[nt], ql[kh], bh);
                    mma16(ca[nt], qh[kh], bl);
                }
            }
        }

        float rs0 = 0.f, rs1 = 0.f;
        uint32_t aAh[8][4], aAl[8][4];
        #pragma unroll
        for (int nt = 0; nt < 16; nt++) {
            int s0 = nt * 8 + 2 * lc;
            float c0 = (s0     <= t0) ? ca[nt][0] : 0.f;
            float c1 = (s0 + 1 <= t0) ? ca[nt][1] : 0.f;
            float c2 = (s0     <= t1) ? ca[nt][2] : 0.f;
            float c3 = (s0 + 1 <= t1) ? ca[nt][3] : 0.f;
            rs0 += c0 + c1;
            rs1 += c2 + c3;
            float h0 = bfr(c0), h1 = bfr(c1), h2 = bfr(c2), h3 = bfr(c3);
            int kb = nt >> 1, half = nt & 1;
            aAh[kb][half * 2 + 0] = pack_bf2(h0, h1);
            aAh[kb][half * 2 + 1] = pack_bf2(h2, h3);
            aAl[kb][half * 2 + 0] = pack_bf2(c0 - h0, c1 - h1);
            aAl[kb][half * 2 + 1] = pack_bf2(c2 - h2, c3 - h3);
        }
        rs0 += __shfl_xor_sync(0xffffffffu, rs0, 1);
        rs0 += __shfl_xor_sync(0xffffffffu, rs0, 2);
        rs1 += __shfl_xor_sync(0xffffffffu, rs1, 1);
        rs1 += __shfl_xor_sync(0xffffffffu, rs1, 2);

        float cb[9][4];
        #pragma unroll
        for (int nt = 0; nt < 9; nt++)
            #pragma unroll
            for (int i = 0; i < 4; i++) cb[nt][i] = 0.f;

        #pragma unroll
        for (int nt = 0; nt < 8; nt++) {
            int n = nt * 8 + lr;
            int swB = nt & 3;
            const uint32_t* vh = smw + OFF_VH + n * 68;
            const uint32_t* vl = smw + OFF_VL + n * 68;
            #pragma unroll
            for (int kh = 0; kh < 8; kh++) {
                if (kh <= wid) {
                    int w = (kh * 8 + lc) ^ swB;
                    uint32_t bh[2] = {vh[w], vh[w + 4]};
                    uint32_t bl[2] = {vl[w], vl[w + 4]};
                    mma16(cb[nt], aAh[kh], bh);
                    mma16(cb[nt], aAl[kh], bh);
                    mma16(cb[nt], aAh[kh], bl);
                }
            }
            const uint32_t* sh = smw + OFF_SH + n * 36 + lc;
            const uint32_t* sl = smw + OFF_SL + n * 36 + lc;
            #pragma unroll
            for (int ks = 0; ks < 4; ks++) {
                uint32_t bh[2] = {sh[ks * 8], sh[ks * 8 + 4]};
                uint32_t bl[2] = {sl[ks * 8], sl[ks * 8 + 4]};
                mma16(cb[nt], qh[ks], bh);
                mma16(cb[nt], ql[ks], bh);
                mma16(cb[nt], qh[ks], bl);
            }
        }
        {
            int n = 64 + lr;
            const uint32_t* sh = smw + OFF_SH + n * 36 + lc;
            const uint32_t* sl = smw + OFF_SL + n * 36 + lc;
            #pragma unroll
            for (int ks = 0; ks < 4; ks++) {
                uint32_t bh[2] = {sh[ks * 8], sh[ks * 8 + 4]};
                uint32_t bl[2] = {sl[ks * 8], sl[ks * 8 + 4]};
                mma16(cb[8], qh[ks], bh);
                mma16(cb[8], ql[ks], bh);
                mma16(cb[8], qh[ks], bl);
            }
        }

        float di0 = __shfl_sync(0xffffffffu, cb[8][0], lane & ~3);
        float di1 = __shfl_sync(0xffffffffu, cb[8][2], lane & ~3);
        float inv0 = 1.f / fmaxf(rs0 + di0, 1e-6f);
        float inv1 = 1.f / fmaxf(rs1 + di1, 1e-6f);

        const int base = (c * CH) * (Dm / 2) + h * 32;
        #pragma unroll
        for (int nt = 0; nt < 8; nt++) {
            int jw = (nt * 8 + 2 * lc) >> 1;
            {
                float o0 = cb[nt][0] * inv0, o1 = cb[nt][1] * inv0;
                float h0 = bfr(o0), h1 = bfr(o1);
                g_Ohi[base + t0 * (Dm / 2) + jw] = pack_bf2(h0, h1);
                g_Olo[base + t0 * (Dm / 2) + jw] = pack_bf2(o0 - h0, o1 - h1);
            }
            {
                float o0 = cb[nt][2] * inv1, o1 = cb[nt][3] * inv1;
                float h0 = bfr(o0), h1 = bfr(o1);
                g_Ohi[base + t1 * (Dm / 2) + jw] = pack_bf2(h0, h1);
                g_Olo[base + t1 * (Dm / 2) + jw] = pack_bf2(o0 - h0, o1 - h1);
            }
        }
    }

    gsync(2);

    // Phase 4: output projection
    {
        const int row0 = (bid & 15) * 128;
        const int col0 = (bid >> 4) * 64;

        float acc[2][4][4];
        gemm_tc((char*)smw, (const char*)g_Ohi, (const char*)g_Olo,
                (const char*)(g_whi + 3 * (Dm * Dm / 2)),
                (const char*)(g_wlo + 3 * (Dm * Dm / 2)),
                row0, col0, acc);

        float* Cs = (float*)smw;
        acc_to_smem(Cs, acc);
        __syncthreads();

        #pragma unroll
        for (int it = 0; it < 8; it++) {
            int idx = tid + it * 256;
            int r = idx >> 4, c4 = (idx & 15) << 2;
            float4 v = *(float4*)&Cs[r * C_STR + c4];
            v.x += bo[col0 + c4 + 0];
            v.y += bo[col0 + c4 + 1];
            v.z += bo[col0 + c4 + 2];
            v.w += bo[col0 + c4 + 3];
            *(float4*)&y[(row0 + r) * Dm + col0 + c4] = v;
        }
    }
}

// ---------------------------------------------------------------------------
extern "C" void kernel_launch(void* const* d_in, const int* in_sizes, int n_in,
                              void* d_out, int out_size)
{
    const float* x  = (const float*)d_in[0];
    const float* Wq = (const float*)d_in[1];
    const float* bq = (const float*)d_in[2];
    const float* Wk = (const float*)d_in[3];
    const float* bk = (const float*)d_in[4];
    const float* Wv = (const float*)d_in[5];
    const float* bv = (const float*)d_in[6];
    const float* Wo = (const float*)d_in[7];
    const float* bo = (const float*)d_in[8];
    float* y = (float*)d_out;

    cudaFuncSetAttribute(qkv3_kernel,
                         cudaFuncAttributeMaxDynamicSharedMemorySize, Q3_SMEM);
    cudaFuncSetAttribute(fused_tail_kernel,
                         cudaFuncAttributeMaxDynamicSharedMemorySize, ATTN_SMEM);

    prep_kernel      <<<dim3(16, 16, 5), 256>>>(x, Wq, Wk, Wv, Wo);
    qkv3_kernel      <<<dim3(T/128, H), 256, Q3_SMEM>>>(bq, bk, bv);
    fused_tail_kernel<<<128, 256, ATTN_SMEM>>>(bo, y);
}